// round 7
// baseline (speedup 1.0000x reference)
#include <cuda_runtime.h>
#include <cuda_bf16.h>
#include <math.h>

#define BATCH 64
#define SEQ   196
#define DIMC  768
#define HEADS 12
#define HD    64
#define QKV3  2304           // 3*DIMC
#define BN    (BATCH*SEQ)    // 12544
#define SCALE 0.125f         // HD^-0.5

// ---------------- scratch (no allocation allowed; __device__ globals) -------
__device__ float g_qkv[(size_t)BATCH * SEQ * QKV3];           // [BN, 2304]
__device__ float g_ao[(size_t)BATCH * SEQ * DIMC];            // [BN, 768]

// ---------------- tf32 helpers ----------------------------------------------
__device__ __forceinline__ unsigned f2tf32(float x) {
    unsigned u;
    asm volatile("cvt.rna.tf32.f32 %0, %1;" : "=r"(u) : "f"(x));
    return u;
}

__device__ __forceinline__ void mma_tf32(float (&d)[4], const unsigned (&a)[4],
                                         const unsigned (&b)[2]) {
    asm volatile(
        "mma.sync.aligned.m16n8k8.row.col.f32.tf32.tf32.f32 "
        "{%0,%1,%2,%3}, {%4,%5,%6,%7}, {%8,%9}, {%0,%1,%2,%3};\n"
        : "+f"(d[0]), "+f"(d[1]), "+f"(d[2]), "+f"(d[3])
        : "r"(a[0]), "r"(a[1]), "r"(a[2]), "r"(a[3]), "r"(b[0]), "r"(b[1]));
}

#define CP_ASYNC16(dst_u32, src_ptr) \
    asm volatile("cp.async.cg.shared.global [%0], [%1], 16;\n" \
                 :: "r"(dst_u32), "l"(src_ptr))
#define CP_COMMIT() asm volatile("cp.async.commit_group;\n" ::: "memory")
#define CP_WAIT0()  asm volatile("cp.async.wait_group 0;\n" ::: "memory")

// ---------------- TF32 GEMM: C[M,N] = A[M,K] @ B[K,N] (+bias) ---------------
// 128x64 block tile, BK=32, 256 threads = 8 warps, warp tile 32x32 (2x4 mma).
// cp.async fills a raw fp32 staging buffer for tile t+1 while tile t computes
// from a tf32 buffer; a vectorized pass converts raw->tf32 once per element.
#define TBM 128
#define TBN 64
#define TBK 32
#define AS_STRIDE 36
#define BS_STRIDE 72
#define A_WORDS (TBM * AS_STRIDE)      // 4608
#define B_WORDS (TBK * BS_STRIDE)      // 2304
#define STAGE_WORDS (A_WORDS + B_WORDS)            // 6912
#define GEMM_SMEM_BYTES (STAGE_WORDS * 2 * 4)      // 55296

__global__ __launch_bounds__(256, 3)
void gemm_tf32_kernel(const float* __restrict__ A, const float* __restrict__ B,
                      const float* __restrict__ bias, float* __restrict__ C,
                      int M, int N, int K, int useBias)
{
    extern __shared__ float gsm[];
    float*    rawA = gsm;                          // raw fp32, stride 36
    float*    rawB = gsm + A_WORDS;                // raw fp32, stride 72
    unsigned* As   = (unsigned*)(gsm + STAGE_WORDS);         // tf32
    unsigned* Bs   = (unsigned*)(gsm + STAGE_WORDS) + A_WORDS;

    const int tid  = threadIdx.x;
    const int lane = tid & 31;
    const int warp = tid >> 5;
    const int r    = lane >> 2;
    const int tq   = lane & 3;
    const int warpM = (warp & 3) * 32;
    const int warpN = (warp >> 2) * 32;

    const int n0 = blockIdx.x * TBN;
    const int m0 = blockIdx.y * TBM;

    // per-thread copy coordinates (16B per cp.async)
    const int a_row = tid >> 3;             // 0..31 (x4 -> 128 rows)
    const int a_kc  = (tid & 7) * 4;        // 0..28
    const int b_kk  = tid >> 4;             // 0..15 (x2 -> 32 rows)
    const int b_nn  = (tid & 15) * 4;       // 0..60

    unsigned a_dst[4], b_dst[2];
#pragma unroll
    for (int i = 0; i < 4; i++)
        a_dst[i] = (unsigned)__cvta_generic_to_shared(
            &rawA[(a_row + i * 32) * AS_STRIDE + a_kc]);
#pragma unroll
    for (int i = 0; i < 2; i++)
        b_dst[i] = (unsigned)__cvta_generic_to_shared(
            &rawB[(b_kk + i * 16) * BS_STRIDE + b_nn]);

    const int nTiles = K / TBK;

    // ---- vectorized raw -> tf32 conversion (once per element)
    const float4* rp = (const float4*)gsm;
    uint4*        tp = (uint4*)(gsm + STAGE_WORDS);

    // ---- prologue: fetch tile 0 into raw, convert
#pragma unroll
    for (int i = 0; i < 4; i++)
        CP_ASYNC16(a_dst[i], A + (size_t)(m0 + a_row + i * 32) * K + a_kc);
#pragma unroll
    for (int i = 0; i < 2; i++)
        CP_ASYNC16(b_dst[i], B + (size_t)b_kk * N + n0 + b_nn +
                              (size_t)(i * 16) * N);
    CP_COMMIT();
    CP_WAIT0();
    __syncthreads();
    for (int i = tid; i < STAGE_WORDS / 4; i += 256) {
        float4 v = rp[i];
        uint4 o;
        o.x = f2tf32(v.x); o.y = f2tf32(v.y);
        o.z = f2tf32(v.z); o.w = f2tf32(v.w);
        tp[i] = o;
    }

    float acc[2][4][4];
#pragma unroll
    for (int i = 0; i < 2; i++)
#pragma unroll
        for (int j = 0; j < 4; j++)
#pragma unroll
            for (int t = 0; t < 4; t++) acc[i][j][t] = 0.f;

    for (int t = 0; t < nTiles; t++) {
        __syncthreads();   // cvt(t) visible to all; raw buffer free for reuse

        const bool havNext = (t + 1 < nTiles);
        if (havNext) {
            const int k0 = (t + 1) * TBK;
#pragma unroll
            for (int i = 0; i < 4; i++)
                CP_ASYNC16(a_dst[i], A + (size_t)(m0 + a_row + i * 32) * K + k0 + a_kc);
#pragma unroll
            for (int i = 0; i < 2; i++)
                CP_ASYNC16(b_dst[i], B + (size_t)(k0 + b_kk + i * 16) * N + n0 + b_nn);
            CP_COMMIT();
        }

        // ---- compute from tf32 buffer (fragment layout identical to R3)
#pragma unroll
        for (int ks = 0; ks < 4; ks++) {
            int kb = ks * 8;
            unsigned afrag[2][4];
#pragma unroll
            for (int mt = 0; mt < 2; mt++) {
                int rb = warpM + mt * 16;
                afrag[mt][0] = As[(rb + r)     * AS_STRIDE + kb + tq];
                afrag[mt][1] = As[(rb + r + 8) * AS_STRIDE + kb + tq];
                afrag[mt][2] = As[(rb + r)     * AS_STRIDE + kb + tq + 4];
                afrag[mt][3] = As[(rb + r + 8) * AS_STRIDE + kb + tq + 4];
            }
            unsigned bfrag[4][2];
#pragma unroll
            for (int nt = 0; nt < 4; nt++) {
                int cb = warpN + nt * 8;
                bfrag[nt][0] = Bs[(kb + tq)     * BS_STRIDE + cb + r];
                bfrag[nt][1] = Bs[(kb + tq + 4) * BS_STRIDE + cb + r];
            }
#pragma unroll
            for (int mt = 0; mt < 2; mt++)
#pragma unroll
                for (int nt = 0; nt < 4; nt++)
                    mma_tf32(acc[mt][nt], afrag[mt], bfrag[nt]);
        }

        if (havNext) {
            CP_WAIT0();        // raw(t+1) landed (per-thread)
            __syncthreads();   // ...for all threads; and all compute(t) reads done
            for (int i = tid; i < STAGE_WORDS / 4; i += 256) {
                float4 v = rp[i];
                uint4 o;
                o.x = f2tf32(v.x); o.y = f2tf32(v.y);
                o.z = f2tf32(v.z); o.w = f2tf32(v.w);
                tp[i] = o;
            }
        }
    }

    // ---- epilogue
#pragma unroll
    for (int mt = 0; mt < 2; mt++) {
#pragma unroll
        for (int nt = 0; nt < 4; nt++) {
            int row = m0 + warpM + mt * 16 + r;
            int col = n0 + warpN + nt * 8 + 2 * tq;
            float2 lo = make_float2(acc[mt][nt][0], acc[mt][nt][1]);
            float2 hi = make_float2(acc[mt][nt][2], acc[mt][nt][3]);
            if (useBias) {
                float2 bv = *(const float2*)(bias + col);
                lo.x += bv.x; lo.y += bv.y;
                hi.x += bv.x; hi.y += bv.y;
            }
            *(float2*)(C + (size_t)row * N + col)       = lo;
            *(float2*)(C + (size_t)(row + 8) * N + col) = hi;
        }
    }
}

// ---------------- fused attention: scores + softmax(+bias) + AV -------------
// One block per (b, h, q-half of 98 rows). 512 threads = 16 warps.
#define QS_OFF 0
#define KV_OFF 7616            // 112*68
#define S_OFF  22016           // 7616 + 14400
#define FUSED_SMEM_BYTES (45760 * 4)   // 183040

__global__ __launch_bounds__(512)
void fused_attn_kernel(const float* __restrict__ qkv,
                       const float* __restrict__ sa,
                       float* __restrict__ ao)
{
    extern __shared__ float sm[];
    unsigned* Qs = (unsigned*)(sm + QS_OFF);   // [112][68] (SCALE pre-folded)
    unsigned* Ks = (unsigned*)(sm + KV_OFF);   // [208][68] (pass 1)
    float*    Vs = sm + KV_OFF;                // [200][72] (pass 3)
    float*    S  = sm + S_OFF;                 // [112][212]

    const int bid = blockIdx.x;
    const int bh = bid >> 1, qb = bid & 1;
    const int b = bh / HEADS, h = bh % HEADS;
    const int q0 = qb * 98;

    const float* Qg = qkv + (size_t)b * SEQ * QKV3 + h * HD;
    const float* Kg = Qg + DIMC;
    const float* Vg = Qg + 2 * DIMC;

    const int tid  = threadIdx.x;
    const int lane = tid & 31;
    const int warp = tid >> 5;
    const int r    = lane >> 2;
    const int tq   = lane & 3;

    // ---- load Q (tf32, pre-scaled by SCALE: exact power of two)
    for (int i = tid; i < 112 * 16; i += 512) {
        int row = i >> 4, c4 = (i & 15) * 4;
        float4 v = make_float4(0.f, 0.f, 0.f, 0.f);
        if (row < 98) v = *(const float4*)(Qg + (size_t)(q0 + row) * QKV3 + c4);
        unsigned* p = &Qs[row * 68 + c4];
        p[0] = f2tf32(v.x * SCALE); p[1] = f2tf32(v.y * SCALE);
        p[2] = f2tf32(v.z * SCALE); p[3] = f2tf32(v.w * SCALE);
    }
    // ---- load K (tf32), rows >= 196 zeroed
    for (int i = tid; i < 208 * 16; i += 512) {
        int row = i >> 4, c4 = (i & 15) * 4;
        float4 v = make_float4(0.f, 0.f, 0.f, 0.f);
        if (row < SEQ) v = *(const float4*)(Kg + (size_t)row * QKV3 + c4);
        unsigned* p = &Ks[row * 68 + c4];
        p[0] = f2tf32(v.x); p[1] = f2tf32(v.y);
        p[2] = f2tf32(v.z); p[3] = f2tf32(v.w);
    }
    __syncthreads();

    // ---- pass 1: S[112][208] = (Q*SCALE) @ K^T
    for (int item = warp; item < 7 * 13; item += 16) {
        int nt = item / 13, mg = item % 13;
        float acc[2][4] = {{0.f,0.f,0.f,0.f},{0.f,0.f,0.f,0.f}};
#pragma unroll
        for (int ks = 0; ks < 8; ks++) {
            int kb = ks * 8;
            unsigned af[4];
            af[0] = Qs[(nt * 16 + r)     * 68 + kb + tq];
            af[1] = Qs[(nt * 16 + r + 8) * 68 + kb + tq];
            af[2] = Qs[(nt * 16 + r)     * 68 + kb + tq + 4];
            af[3] = Qs[(nt * 16 + r + 8) * 68 + kb + tq + 4];
#pragma unroll
            for (int mt = 0; mt < 2; mt++) {
                int cb = mg * 16 + mt * 8;
                unsigned bf[2];
                bf[0] = Ks[(cb + r) * 68 + kb + tq];
                bf[1] = Ks[(cb + r) * 68 + kb + tq + 4];
                mma_tf32(acc[mt], af, bf);
            }
        }
#pragma unroll
        for (int mt = 0; mt < 2; mt++) {
            int c = mg * 16 + mt * 8 + 2 * tq;
            int row = nt * 16 + r;
            S[row * 212 + c]           = acc[mt][0];
            S[row * 212 + c + 1]       = acc[mt][1];
            S[(row + 8) * 212 + c]     = acc[mt][2];
            S[(row + 8) * 212 + c + 1] = acc[mt][3];
        }
    }
    __syncthreads();

    // ---- load V (fp32)
    for (int i = tid; i < 200 * 16; i += 512) {
        int row = i >> 4, c4 = (i & 15) * 4;
        float4 v = make_float4(0.f, 0.f, 0.f, 0.f);
        if (row < SEQ) v = *(const float4*)(Vg + (size_t)row * QKV3 + c4);
        *(float4*)&Vs[row * 72 + c4] = v;
    }

    // ---- pass 2: softmax rows (cols<196) + static_a bias, in place
    for (int row = warp; row < 98; row += 16) {
        float* Sr = S + row * 212;
        float vals[7];
        float mx = -INFINITY;
#pragma unroll
        for (int j = 0; j < 7; j++) {
            int c = lane + 32 * j;
            vals[j] = (c < SEQ) ? Sr[c] : -INFINITY;
            mx = fmaxf(mx, vals[j]);
        }
#pragma unroll
        for (int s = 16; s; s >>= 1) mx = fmaxf(mx, __shfl_xor_sync(0xffffffffu, mx, s));
        float sum = 0.f;
#pragma unroll
        for (int j = 0; j < 7; j++) { vals[j] = __expf(vals[j] - mx); sum += vals[j]; }
#pragma unroll
        for (int s = 16; s; s >>= 1) sum += __shfl_xor_sync(0xffffffffu, sum, s);
        float inv = 1.f / sum;
        const float* ar = sa + ((size_t)h * SEQ + q0 + row) * SEQ;
#pragma unroll
        for (int j = 0; j < 7; j++) {
            int c = lane + 32 * j;
            if (c < SEQ) Sr[c] = vals[j] * inv + ar[c];
        }
    }
    __syncthreads();

    // ---- pass 3: out = S(98x196) @ V(196x64), 3xTF32 split
    float* og = ao + (size_t)b * SEQ * DIMC + h * HD;
    for (int item = warp; item < 7 * 4; item += 16) {
        int nt = item >> 2, cg = item & 3;
        float acc[2][4] = {{0.f,0.f,0.f,0.f},{0.f,0.f,0.f,0.f}};
        for (int ks = 0; ks < 25; ks++) {
            int kb = ks * 8;
            float av[4];
            av[0] = S[(nt * 16 + r)     * 212 + kb + tq];
            av[1] = S[(nt * 16 + r + 8) * 212 + kb + tq];
            av[2] = S[(nt * 16 + r)     * 212 + kb + tq + 4];
            av[3] = S[(nt * 16 + r + 8) * 212 + kb + tq + 4];
            unsigned ahi[4], alo[4];
#pragma unroll
            for (int i = 0; i < 4; i++) {
                ahi[i] = f2tf32(av[i]);
                alo[i] = f2tf32(av[i] - __uint_as_float(ahi[i]));
            }
#pragma unroll
            for (int mt = 0; mt < 2; mt++) {
                int cb = cg * 16 + mt * 8;
                float b0 = Vs[(kb + tq)     * 72 + cb + r];
                float b1 = Vs[(kb + tq + 4) * 72 + cb + r];
                unsigned bhi[2], blo[2];
                bhi[0] = f2tf32(b0); bhi[1] = f2tf32(b1);
                blo[0] = f2tf32(b0 - __uint_as_float(bhi[0]));
                blo[1] = f2tf32(b1 - __uint_as_float(bhi[1]));
                mma_tf32(acc[mt], ahi, bhi);
                mma_tf32(acc[mt], ahi, blo);
                mma_tf32(acc[mt], alo, bhi);
            }
        }
#pragma unroll
        for (int mt = 0; mt < 2; mt++) {
            int c = cg * 16 + mt * 8 + 2 * tq;
            int row = nt * 16 + r;
            if (row < 98)
                *(float2*)(og + (size_t)(q0 + row) * DIMC + c) =
                    make_float2(acc[mt][0], acc[mt][1]);
            if (row + 8 < 98)
                *(float2*)(og + (size_t)(q0 + row + 8) * DIMC + c) =
                    make_float2(acc[mt][2], acc[mt][3]);
        }
    }
}

// ---------------- launch ----------------------------------------------------
extern "C" void kernel_launch(void* const* d_in, const int* in_sizes, int n_in,
                              void* d_out, int out_size)
{
    const float* x     = (const float*)d_in[0];  // [64,196,768]
    const float* Wqkv  = (const float*)d_in[1];  // [768,2304]
    const float* sa    = (const float*)d_in[2];  // [1,12,196,196]
    const float* Wproj = (const float*)d_in[3];  // [768,768]
    const float* bproj = (const float*)d_in[4];  // [768]
    float* out = (float*)d_out;                  // [64,196,768]

    void *p_qkv, *p_ao;
    cudaGetSymbolAddress(&p_qkv, g_qkv);
    cudaGetSymbolAddress(&p_ao, g_ao);
    float* qkv = (float*)p_qkv;
    float* ao  = (float*)p_ao;

    static int smem_set = 0;
    if (!smem_set) {
        cudaFuncSetAttribute(fused_attn_kernel,
                             cudaFuncAttributeMaxDynamicSharedMemorySize,
                             FUSED_SMEM_BYTES);
        cudaFuncSetAttribute(gemm_tf32_kernel,
                             cudaFuncAttributeMaxDynamicSharedMemorySize,
                             GEMM_SMEM_BYTES);
        smem_set = 1;
    }

    // 1) QKV GEMM: [12544,768] @ [768,2304]  (tf32, cp.async + cvt pass)
    gemm_tf32_kernel<<<dim3(QKV3 / TBN, BN / TBM), 256, GEMM_SMEM_BYTES>>>(
        x, Wqkv, nullptr, qkv, BN, QKV3, DIMC, 0);
    // 2-4) fused scores + softmax(+static_a) + AV
    fused_attn_kernel<<<BATCH * HEADS * 2, 512, FUSED_SMEM_BYTES>>>(qkv, sa, ao);
    // 5) output projection + bias (tf32, cp.async + cvt pass)
    gemm_tf32_kernel<<<dim3(DIMC / TBN, BN / TBM), 256, GEMM_SMEM_BYTES>>>(
        ao, Wproj, bproj, out, BN, DIMC, DIMC, 1);
}

// round 8
// speedup vs baseline: 1.0659x; 1.0659x over previous
#include <cuda_runtime.h>
#include <cuda_bf16.h>
#include <math.h>

#define BATCH 64
#define SEQ   196
#define DIMC  768
#define HEADS 12
#define HD    64
#define QKV3  2304           // 3*DIMC
#define BN    (BATCH*SEQ)    // 12544
#define SCALE 0.125f         // HD^-0.5

// ---------------- scratch (no allocation allowed; __device__ globals) -------
__device__ float g_qkv[(size_t)BATCH * SEQ * QKV3];           // [BN, 2304]
__device__ float g_ao[(size_t)BATCH * SEQ * DIMC];            // [BN, 768]

// ---------------- tf32 helpers ----------------------------------------------
__device__ __forceinline__ unsigned f2tf32(float x) {
    unsigned u;
    asm volatile("cvt.rna.tf32.f32 %0, %1;" : "=r"(u) : "f"(x));
    return u;
}

__device__ __forceinline__ void mma_tf32(float (&d)[4], const unsigned (&a)[4],
                                         const unsigned (&b)[2]) {
    asm volatile(
        "mma.sync.aligned.m16n8k8.row.col.f32.tf32.tf32.f32 "
        "{%0,%1,%2,%3}, {%4,%5,%6,%7}, {%8,%9}, {%0,%1,%2,%3};\n"
        : "+f"(d[0]), "+f"(d[1]), "+f"(d[2]), "+f"(d[3])
        : "r"(a[0]), "r"(a[1]), "r"(a[2]), "r"(a[3]), "r"(b[0]), "r"(b[1]));
}

// ---------------- TF32 GEMM: C[M,N] = A[M,K] @ B[K,N] (+bias) ---------------
// 128x64 block tile, BK=32, 256 threads = 8 warps, warp tile 32x32 (2x4 mma).
// R3 structure (synchronous, single-buffer) + forced 4 CTAs/SM for occupancy.
#define TBM 128
#define TBN 64
#define TBK 32
#define AS_STRIDE 36   // frag banks (4r+tq) all distinct
#define BS_STRIDE 72   // frag banks (8tq+r) all distinct

__global__ __launch_bounds__(256, 4)
void gemm_tf32_kernel(const float* __restrict__ A, const float* __restrict__ B,
                      const float* __restrict__ bias, float* __restrict__ C,
                      int M, int N, int K, int useBias)
{
    __shared__ unsigned As[TBM * AS_STRIDE];   // [m][k], stride 36
    __shared__ unsigned Bs[TBK * BS_STRIDE];   // [k][n], stride 72

    const int tid  = threadIdx.x;
    const int lane = tid & 31;
    const int warp = tid >> 5;
    const int r    = lane >> 2;
    const int tq   = lane & 3;
    const int warpM = (warp & 3) * 32;
    const int warpN = (warp >> 2) * 32;

    const int n0 = blockIdx.x * TBN;
    const int m0 = blockIdx.y * TBM;

    float acc[2][4][4];
#pragma unroll
    for (int i = 0; i < 2; i++)
#pragma unroll
        for (int j = 0; j < 4; j++)
#pragma unroll
            for (int t = 0; t < 4; t++) acc[i][j][t] = 0.f;

    for (int k0 = 0; k0 < K; k0 += TBK) {
        // ---- load A tile: 128 rows x 32 k = 1024 float4 (4 per thread)
#pragma unroll
        for (int i = 0; i < 4; i++) {
            int f   = tid + i * 256;
            int row = f >> 3;
            int kk  = (f & 7) * 4;
            float4 v = *(const float4*)(A + (size_t)(m0 + row) * K + k0 + kk);
            unsigned* p = &As[row * AS_STRIDE + kk];
            p[0] = f2tf32(v.x); p[1] = f2tf32(v.y);
            p[2] = f2tf32(v.z); p[3] = f2tf32(v.w);
        }
        // ---- load B tile: 32 k x 64 n = 512 float4 (2 per thread)
#pragma unroll
        for (int i = 0; i < 2; i++) {
            int f   = tid + i * 256;
            int kk  = f >> 4;
            int nn  = (f & 15) * 4;
            float4 v = *(const float4*)(B + (size_t)(k0 + kk) * N + n0 + nn);
            unsigned* p = &Bs[kk * BS_STRIDE + nn];
            p[0] = f2tf32(v.x); p[1] = f2tf32(v.y);
            p[2] = f2tf32(v.z); p[3] = f2tf32(v.w);
        }
        __syncthreads();

        // ---- compute: 4 k-steps of 8
#pragma unroll
        for (int ks = 0; ks < 4; ks++) {
            int kb = ks * 8;
            unsigned afrag[2][4];
#pragma unroll
            for (int mt = 0; mt < 2; mt++) {
                int rb = warpM + mt * 16;
                afrag[mt][0] = As[(rb + r)     * AS_STRIDE + kb + tq];
                afrag[mt][1] = As[(rb + r + 8) * AS_STRIDE + kb + tq];
                afrag[mt][2] = As[(rb + r)     * AS_STRIDE + kb + tq + 4];
                afrag[mt][3] = As[(rb + r + 8) * AS_STRIDE + kb + tq + 4];
            }
            unsigned bfrag[4][2];
#pragma unroll
            for (int nt = 0; nt < 4; nt++) {
                int cb = warpN + nt * 8;
                bfrag[nt][0] = Bs[(kb + tq)     * BS_STRIDE + cb + r];
                bfrag[nt][1] = Bs[(kb + tq + 4) * BS_STRIDE + cb + r];
            }
#pragma unroll
            for (int mt = 0; mt < 2; mt++)
#pragma unroll
                for (int nt = 0; nt < 4; nt++)
                    mma_tf32(acc[mt][nt], afrag[mt], bfrag[nt]);
        }
        __syncthreads();
    }

    // ---- epilogue: c0/c1 at (r, 2tq), c2/c3 at (r+8, 2tq)
#pragma unroll
    for (int mt = 0; mt < 2; mt++) {
#pragma unroll
        for (int nt = 0; nt < 4; nt++) {
            int row = m0 + warpM + mt * 16 + r;
            int col = n0 + warpN + nt * 8 + 2 * tq;
            float2 lo = make_float2(acc[mt][nt][0], acc[mt][nt][1]);
            float2 hi = make_float2(acc[mt][nt][2], acc[mt][nt][3]);
            if (useBias) {
                float2 bv = *(const float2*)(bias + col);
                lo.x += bv.x; lo.y += bv.y;
                hi.x += bv.x; hi.y += bv.y;
            }
            *(float2*)(C + (size_t)row * N + col)       = lo;
            *(float2*)(C + (size_t)(row + 8) * N + col) = hi;
        }
    }
}

// ---------------- fused attention: scores + softmax(+bias) + AV -------------
// One block per (b, h, q-half of 98 rows). 512 threads = 16 warps.
#define QS_OFF 0
#define KV_OFF 7616            // 112*68
#define S_OFF  22016           // 7616 + 14400
#define FUSED_SMEM_BYTES (45760 * 4)   // 183040

__global__ __launch_bounds__(512)
void fused_attn_kernel(const float* __restrict__ qkv,
                       const float* __restrict__ sa,
                       float* __restrict__ ao)
{
    extern __shared__ float sm[];
    unsigned* Qs = (unsigned*)(sm + QS_OFF);   // [112][68] (SCALE pre-folded)
    unsigned* Ks = (unsigned*)(sm + KV_OFF);   // [208][68] (pass 1)
    float*    Vs = sm + KV_OFF;                // [200][72] (pass 3)
    float*    S  = sm + S_OFF;                 // [112][212]

    const int bid = blockIdx.x;
    const int bh = bid >> 1, qb = bid & 1;
    const int b = bh / HEADS, h = bh % HEADS;
    const int q0 = qb * 98;

    const float* Qg = qkv + (size_t)b * SEQ * QKV3 + h * HD;
    const float* Kg = Qg + DIMC;
    const float* Vg = Qg + 2 * DIMC;

    const int tid  = threadIdx.x;
    const int lane = tid & 31;
    const int warp = tid >> 5;
    const int r    = lane >> 2;
    const int tq   = lane & 3;

    // ---- load Q (tf32, pre-scaled by SCALE: exact power of two)
    for (int i = tid; i < 112 * 16; i += 512) {
        int row = i >> 4, c4 = (i & 15) * 4;
        float4 v = make_float4(0.f, 0.f, 0.f, 0.f);
        if (row < 98) v = *(const float4*)(Qg + (size_t)(q0 + row) * QKV3 + c4);
        unsigned* p = &Qs[row * 68 + c4];
        p[0] = f2tf32(v.x * SCALE); p[1] = f2tf32(v.y * SCALE);
        p[2] = f2tf32(v.z * SCALE); p[3] = f2tf32(v.w * SCALE);
    }
    // ---- load K (tf32), rows >= 196 zeroed
    for (int i = tid; i < 208 * 16; i += 512) {
        int row = i >> 4, c4 = (i & 15) * 4;
        float4 v = make_float4(0.f, 0.f, 0.f, 0.f);
        if (row < SEQ) v = *(const float4*)(Kg + (size_t)row * QKV3 + c4);
        unsigned* p = &Ks[row * 68 + c4];
        p[0] = f2tf32(v.x); p[1] = f2tf32(v.y);
        p[2] = f2tf32(v.z); p[3] = f2tf32(v.w);
    }
    __syncthreads();

    // ---- pass 1: S[112][208] = (Q*SCALE) @ K^T
    for (int item = warp; item < 7 * 13; item += 16) {
        int nt = item / 13, mg = item % 13;
        float acc[2][4] = {{0.f,0.f,0.f,0.f},{0.f,0.f,0.f,0.f}};
#pragma unroll
        for (int ks = 0; ks < 8; ks++) {
            int kb = ks * 8;
            unsigned af[4];
            af[0] = Qs[(nt * 16 + r)     * 68 + kb + tq];
            af[1] = Qs[(nt * 16 + r + 8) * 68 + kb + tq];
            af[2] = Qs[(nt * 16 + r)     * 68 + kb + tq + 4];
            af[3] = Qs[(nt * 16 + r + 8) * 68 + kb + tq + 4];
#pragma unroll
            for (int mt = 0; mt < 2; mt++) {
                int cb = mg * 16 + mt * 8;
                unsigned bf[2];
                bf[0] = Ks[(cb + r) * 68 + kb + tq];
                bf[1] = Ks[(cb + r) * 68 + kb + tq + 4];
                mma_tf32(acc[mt], af, bf);
            }
        }
#pragma unroll
        for (int mt = 0; mt < 2; mt++) {
            int c = mg * 16 + mt * 8 + 2 * tq;
            int row = nt * 16 + r;
            S[row * 212 + c]           = acc[mt][0];
            S[row * 212 + c + 1]       = acc[mt][1];
            S[(row + 8) * 212 + c]     = acc[mt][2];
            S[(row + 8) * 212 + c + 1] = acc[mt][3];
        }
    }
    __syncthreads();

    // ---- load V (fp32)
    for (int i = tid; i < 200 * 16; i += 512) {
        int row = i >> 4, c4 = (i & 15) * 4;
        float4 v = make_float4(0.f, 0.f, 0.f, 0.f);
        if (row < SEQ) v = *(const float4*)(Vg + (size_t)row * QKV3 + c4);
        *(float4*)&Vs[row * 72 + c4] = v;
    }

    // ---- pass 2: softmax rows (cols<196) + static_a bias, in place
    for (int row = warp; row < 98; row += 16) {
        float* Sr = S + row * 212;
        float vals[7];
        float mx = -INFINITY;
#pragma unroll
        for (int j = 0; j < 7; j++) {
            int c = lane + 32 * j;
            vals[j] = (c < SEQ) ? Sr[c] : -INFINITY;
            mx = fmaxf(mx, vals[j]);
        }
#pragma unroll
        for (int s = 16; s; s >>= 1) mx = fmaxf(mx, __shfl_xor_sync(0xffffffffu, mx, s));
        float sum = 0.f;
#pragma unroll
        for (int j = 0; j < 7; j++) { vals[j] = __expf(vals[j] - mx); sum += vals[j]; }
#pragma unroll
        for (int s = 16; s; s >>= 1) sum += __shfl_xor_sync(0xffffffffu, sum, s);
        float inv = 1.f / sum;
        const float* ar = sa + ((size_t)h * SEQ + q0 + row) * SEQ;
#pragma unroll
        for (int j = 0; j < 7; j++) {
            int c = lane + 32 * j;
            if (c < SEQ) Sr[c] = vals[j] * inv + ar[c];
        }
    }
    __syncthreads();

    // ---- pass 3: out = S(98x196) @ V(196x64), 3xTF32 split
    float* og = ao + (size_t)b * SEQ * DIMC + h * HD;
    for (int item = warp; item < 7 * 4; item += 16) {
        int nt = item >> 2, cg = item & 3;
        float acc[2][4] = {{0.f,0.f,0.f,0.f},{0.f,0.f,0.f,0.f}};
        for (int ks = 0; ks < 25; ks++) {
            int kb = ks * 8;
            float av[4];
            av[0] = S[(nt * 16 + r)     * 212 + kb + tq];
            av[1] = S[(nt * 16 + r + 8) * 212 + kb + tq];
            av[2] = S[(nt * 16 + r)     * 212 + kb + tq + 4];
            av[3] = S[(nt * 16 + r + 8) * 212 + kb + tq + 4];
            unsigned ahi[4], alo[4];
#pragma unroll
            for (int i = 0; i < 4; i++) {
                ahi[i] = f2tf32(av[i]);
                alo[i] = f2tf32(av[i] - __uint_as_float(ahi[i]));
            }
#pragma unroll
            for (int mt = 0; mt < 2; mt++) {
                int cb = cg * 16 + mt * 8;
                float b0 = Vs[(kb + tq)     * 72 + cb + r];
                float b1 = Vs[(kb + tq + 4) * 72 + cb + r];
                unsigned bhi[2], blo[2];
                bhi[0] = f2tf32(b0); bhi[1] = f2tf32(b1);
                blo[0] = f2tf32(b0 - __uint_as_float(bhi[0]));
                blo[1] = f2tf32(b1 - __uint_as_float(bhi[1]));
                mma_tf32(acc[mt], ahi, bhi);
                mma_tf32(acc[mt], ahi, blo);
                mma_tf32(acc[mt], alo, bhi);
            }
        }
#pragma unroll
        for (int mt = 0; mt < 2; mt++) {
            int c = cg * 16 + mt * 8 + 2 * tq;
            int row = nt * 16 + r;
            if (row < 98)
                *(float2*)(og + (size_t)(q0 + row) * DIMC + c) =
                    make_float2(acc[mt][0], acc[mt][1]);
            if (row + 8 < 98)
                *(float2*)(og + (size_t)(q0 + row + 8) * DIMC + c) =
                    make_float2(acc[mt][2], acc[mt][3]);
        }
    }
}

// ---------------- launch ----------------------------------------------------
extern "C" void kernel_launch(void* const* d_in, const int* in_sizes, int n_in,
                              void* d_out, int out_size)
{
    const float* x     = (const float*)d_in[0];  // [64,196,768]
    const float* Wqkv  = (const float*)d_in[1];  // [768,2304]
    const float* sa    = (const float*)d_in[2];  // [1,12,196,196]
    const float* Wproj = (const float*)d_in[3];  // [768,768]
    const float* bproj = (const float*)d_in[4];  // [768]
    float* out = (float*)d_out;                  // [64,196,768]

    void *p_qkv, *p_ao;
    cudaGetSymbolAddress(&p_qkv, g_qkv);
    cudaGetSymbolAddress(&p_ao, g_ao);
    float* qkv = (float*)p_qkv;
    float* ao  = (float*)p_ao;

    static int smem_set = 0;
    if (!smem_set) {
        cudaFuncSetAttribute(fused_attn_kernel,
                             cudaFuncAttributeMaxDynamicSharedMemorySize,
                             FUSED_SMEM_BYTES);
        smem_set = 1;
    }

    // 1) QKV GEMM: [12544,768] @ [768,2304]  (tf32, 4 CTAs/SM)
    gemm_tf32_kernel<<<dim3(QKV3 / TBN, BN / TBM), 256>>>(x, Wqkv, nullptr, qkv,
                                                          BN, QKV3, DIMC, 0);
    // 2-4) fused scores + softmax(+static_a) + AV
    fused_attn_kernel<<<BATCH * HEADS * 2, 512, FUSED_SMEM_BYTES>>>(qkv, sa, ao);
    // 5) output projection + bias (tf32, 4 CTAs/SM)
    gemm_tf32_kernel<<<dim3(DIMC / TBN, BN / TBM), 256>>>(ao, Wproj, bproj, out,
                                                          BN, DIMC, DIMC, 1);
}

// round 9
// speedup vs baseline: 1.2720x; 1.1934x over previous
#include <cuda_runtime.h>
#include <cuda_bf16.h>
#include <math.h>

#define BATCH 64
#define SEQ   196
#define DIMC  768
#define HEADS 12
#define HD    64
#define QKV3  2304           // 3*DIMC
#define BN    (BATCH*SEQ)    // 12544
#define SCALE 0.125f         // HD^-0.5

// ---------------- scratch (no allocation allowed; __device__ globals) -------
__device__ float g_qkv[(size_t)BATCH * SEQ * QKV3];           // [BN, 2304]
__device__ float g_ao[(size_t)BATCH * SEQ * DIMC];            // [BN, 768]

// ---------------- tf32 helpers ----------------------------------------------
__device__ __forceinline__ unsigned f2tf32(float x) {
    unsigned u;
    asm volatile("cvt.rna.tf32.f32 %0, %1;" : "=r"(u) : "f"(x));
    return u;
}

__device__ __forceinline__ void mma_tf32(float (&d)[4], const unsigned (&a)[4],
                                         const unsigned (&b)[2]) {
    asm volatile(
        "mma.sync.aligned.m16n8k8.row.col.f32.tf32.tf32.f32 "
        "{%0,%1,%2,%3}, {%4,%5,%6,%7}, {%8,%9}, {%0,%1,%2,%3};\n"
        : "+f"(d[0]), "+f"(d[1]), "+f"(d[2]), "+f"(d[3])
        : "r"(a[0]), "r"(a[1]), "r"(a[2]), "r"(a[3]), "r"(b[0]), "r"(b[1]));
}

// ---------------- TF32 GEMM: C[M,N] = A[M,K] @ B[K,N] (+bias) ---------------
// 128x128 block tile, BK=32, 256 threads = 8 warps (4M x 2N), warp tile 32x64.
// Wider tile cuts smem-crossbar bytes per flop by 41% vs 128x64 (the measured
// bottleneck: tensor% saturates ~40% independent of occupancy).
#define TBM 128
#define TBN 128
#define TBK 32
#define AS_STRIDE 36    // %32==4 -> A frag banks (4r+tq) all distinct
#define BS_STRIDE 136   // %32==8 -> B frag banks (8tq+r) all distinct

__global__ __launch_bounds__(256, 2)
void gemm_tf32_kernel(const float* __restrict__ A, const float* __restrict__ B,
                      const float* __restrict__ bias, float* __restrict__ C,
                      int M, int N, int K, int useBias)
{
    __shared__ unsigned As[TBM * AS_STRIDE];   // [m][k]
    __shared__ unsigned Bs[TBK * BS_STRIDE];   // [k][n]

    const int tid  = threadIdx.x;
    const int lane = tid & 31;
    const int warp = tid >> 5;
    const int r    = lane >> 2;
    const int tq   = lane & 3;
    const int warpM = (warp & 3) * 32;     // 4 warps in M
    const int warpN = (warp >> 2) * 64;    // 2 warps in N, 64 cols each

    const int n0 = blockIdx.x * TBN;
    const int m0 = blockIdx.y * TBM;

    float acc[2][8][4];
#pragma unroll
    for (int i = 0; i < 2; i++)
#pragma unroll
        for (int j = 0; j < 8; j++)
#pragma unroll
            for (int t = 0; t < 4; t++) acc[i][j][t] = 0.f;

    for (int k0 = 0; k0 < K; k0 += TBK) {
        // ---- load A tile: 128 rows x 32 k = 1024 float4 (4 per thread)
#pragma unroll
        for (int i = 0; i < 4; i++) {
            int f   = tid + i * 256;
            int row = f >> 3;                 // 0..127
            int kk  = (f & 7) * 4;            // 0..28
            float4 v = *(const float4*)(A + (size_t)(m0 + row) * K + k0 + kk);
            uint4 o;
            o.x = f2tf32(v.x); o.y = f2tf32(v.y);
            o.z = f2tf32(v.z); o.w = f2tf32(v.w);
            *(uint4*)&As[row * AS_STRIDE + kk] = o;
        }
        // ---- load B tile: 32 k x 128 n = 1024 float4 (4 per thread)
#pragma unroll
        for (int i = 0; i < 4; i++) {
            int f   = tid + i * 256;
            int kk  = f >> 5;                 // 0..31
            int nn  = (f & 31) * 4;           // 0..124
            float4 v = *(const float4*)(B + (size_t)(k0 + kk) * N + n0 + nn);
            uint4 o;
            o.x = f2tf32(v.x); o.y = f2tf32(v.y);
            o.z = f2tf32(v.z); o.w = f2tf32(v.w);
            *(uint4*)&Bs[kk * BS_STRIDE + nn] = o;
        }
        __syncthreads();

        // ---- compute: 4 k-steps of 8
#pragma unroll
        for (int ks = 0; ks < 4; ks++) {
            int kb = ks * 8;
            unsigned afrag[2][4];
#pragma unroll
            for (int mt = 0; mt < 2; mt++) {
                int rb = warpM + mt * 16;
                afrag[mt][0] = As[(rb + r)     * AS_STRIDE + kb + tq];
                afrag[mt][1] = As[(rb + r + 8) * AS_STRIDE + kb + tq];
                afrag[mt][2] = As[(rb + r)     * AS_STRIDE + kb + tq + 4];
                afrag[mt][3] = As[(rb + r + 8) * AS_STRIDE + kb + tq + 4];
            }
            unsigned bfrag[8][2];
#pragma unroll
            for (int nt = 0; nt < 8; nt++) {
                int cb = warpN + nt * 8;
                bfrag[nt][0] = Bs[(kb + tq)     * BS_STRIDE + cb + r];
                bfrag[nt][1] = Bs[(kb + tq + 4) * BS_STRIDE + cb + r];
            }
#pragma unroll
            for (int mt = 0; mt < 2; mt++)
#pragma unroll
                for (int nt = 0; nt < 8; nt++)
                    mma_tf32(acc[mt][nt], afrag[mt], bfrag[nt]);
        }
        __syncthreads();
    }

    // ---- epilogue: c0/c1 at (r, 2tq), c2/c3 at (r+8, 2tq)
#pragma unroll
    for (int mt = 0; mt < 2; mt++) {
#pragma unroll
        for (int nt = 0; nt < 8; nt++) {
            int row = m0 + warpM + mt * 16 + r;
            int col = n0 + warpN + nt * 8 + 2 * tq;
            float2 lo = make_float2(acc[mt][nt][0], acc[mt][nt][1]);
            float2 hi = make_float2(acc[mt][nt][2], acc[mt][nt][3]);
            if (useBias) {
                float2 bv = *(const float2*)(bias + col);
                lo.x += bv.x; lo.y += bv.y;
                hi.x += bv.x; hi.y += bv.y;
            }
            *(float2*)(C + (size_t)row * N + col)       = lo;
            *(float2*)(C + (size_t)(row + 8) * N + col) = hi;
        }
    }
}

// ---------------- fused attention: scores + softmax(+bias) + AV -------------
// One block per (b, h, q-half of 98 rows). 512 threads = 16 warps.
#define QS_OFF 0
#define KV_OFF 7616            // 112*68
#define S_OFF  22016           // 7616 + 14400
#define FUSED_SMEM_BYTES (45760 * 4)   // 183040

__global__ __launch_bounds__(512)
void fused_attn_kernel(const float* __restrict__ qkv,
                       const float* __restrict__ sa,
                       float* __restrict__ ao)
{
    extern __shared__ float sm[];
    unsigned* Qs = (unsigned*)(sm + QS_OFF);   // [112][68] (SCALE pre-folded)
    unsigned* Ks = (unsigned*)(sm + KV_OFF);   // [208][68] (pass 1)
    float*    Vs = sm + KV_OFF;                // [200][72] (pass 3)
    float*    S  = sm + S_OFF;                 // [112][212]

    const int bid = blockIdx.x;
    const int bh = bid >> 1, qb = bid & 1;
    const int b = bh / HEADS, h = bh % HEADS;
    const int q0 = qb * 98;

    const float* Qg = qkv + (size_t)b * SEQ * QKV3 + h * HD;
    const float* Kg = Qg + DIMC;
    const float* Vg = Qg + 2 * DIMC;

    const int tid  = threadIdx.x;
    const int lane = tid & 31;
    const int warp = tid >> 5;
    const int r    = lane >> 2;
    const int tq   = lane & 3;

    // ---- load Q (tf32, pre-scaled by SCALE: exact power of two)
    for (int i = tid; i < 112 * 16; i += 512) {
        int row = i >> 4, c4 = (i & 15) * 4;
        float4 v = make_float4(0.f, 0.f, 0.f, 0.f);
        if (row < 98) v = *(const float4*)(Qg + (size_t)(q0 + row) * QKV3 + c4);
        unsigned* p = &Qs[row * 68 + c4];
        p[0] = f2tf32(v.x * SCALE); p[1] = f2tf32(v.y * SCALE);
        p[2] = f2tf32(v.z * SCALE); p[3] = f2tf32(v.w * SCALE);
    }
    // ---- load K (tf32), rows >= 196 zeroed
    for (int i = tid; i < 208 * 16; i += 512) {
        int row = i >> 4, c4 = (i & 15) * 4;
        float4 v = make_float4(0.f, 0.f, 0.f, 0.f);
        if (row < SEQ) v = *(const float4*)(Kg + (size_t)row * QKV3 + c4);
        unsigned* p = &Ks[row * 68 + c4];
        p[0] = f2tf32(v.x); p[1] = f2tf32(v.y);
        p[2] = f2tf32(v.z); p[3] = f2tf32(v.w);
    }
    __syncthreads();

    // ---- pass 1: S[112][208] = (Q*SCALE) @ K^T
    for (int item = warp; item < 7 * 13; item += 16) {
        int nt = item / 13, mg = item % 13;
        float acc[2][4] = {{0.f,0.f,0.f,0.f},{0.f,0.f,0.f,0.f}};
#pragma unroll
        for (int ks = 0; ks < 8; ks++) {
            int kb = ks * 8;
            unsigned af[4];
            af[0] = Qs[(nt * 16 + r)     * 68 + kb + tq];
            af[1] = Qs[(nt * 16 + r + 8) * 68 + kb + tq];
            af[2] = Qs[(nt * 16 + r)     * 68 + kb + tq + 4];
            af[3] = Qs[(nt * 16 + r + 8) * 68 + kb + tq + 4];
#pragma unroll
            for (int mt = 0; mt < 2; mt++) {
                int cb = mg * 16 + mt * 8;
                unsigned bf[2];
                bf[0] = Ks[(cb + r) * 68 + kb + tq];
                bf[1] = Ks[(cb + r) * 68 + kb + tq + 4];
                mma_tf32(acc[mt], af, bf);
            }
        }
#pragma unroll
        for (int mt = 0; mt < 2; mt++) {
            int c = mg * 16 + mt * 8 + 2 * tq;
            int row = nt * 16 + r;
            S[row * 212 + c]           = acc[mt][0];
            S[row * 212 + c + 1]       = acc[mt][1];
            S[(row + 8) * 212 + c]     = acc[mt][2];
            S[(row + 8) * 212 + c + 1] = acc[mt][3];
        }
    }
    __syncthreads();

    // ---- load V (fp32)
    for (int i = tid; i < 200 * 16; i += 512) {
        int row = i >> 4, c4 = (i & 15) * 4;
        float4 v = make_float4(0.f, 0.f, 0.f, 0.f);
        if (row < SEQ) v = *(const float4*)(Vg + (size_t)row * QKV3 + c4);
        *(float4*)&Vs[row * 72 + c4] = v;
    }

    // ---- pass 2: softmax rows (cols<196) + static_a bias, in place
    for (int row = warp; row < 98; row += 16) {
        float* Sr = S + row * 212;
        float vals[7];
        float mx = -INFINITY;
#pragma unroll
        for (int j = 0; j < 7; j++) {
            int c = lane + 32 * j;
            vals[j] = (c < SEQ) ? Sr[c] : -INFINITY;
            mx = fmaxf(mx, vals[j]);
        }
#pragma unroll
        for (int s = 16; s; s >>= 1) mx = fmaxf(mx, __shfl_xor_sync(0xffffffffu, mx, s));
        float sum = 0.f;
#pragma unroll
        for (int j = 0; j < 7; j++) { vals[j] = __expf(vals[j] - mx); sum += vals[j]; }
#pragma unroll
        for (int s = 16; s; s >>= 1) sum += __shfl_xor_sync(0xffffffffu, sum, s);
        float inv = 1.f / sum;
        const float* ar = sa + ((size_t)h * SEQ + q0 + row) * SEQ;
#pragma unroll
        for (int j = 0; j < 7; j++) {
            int c = lane + 32 * j;
            if (c < SEQ) Sr[c] = vals[j] * inv + ar[c];
        }
    }
    __syncthreads();

    // ---- pass 3: out = S(98x196) @ V(196x64), 3xTF32 split
    float* og = ao + (size_t)b * SEQ * DIMC + h * HD;
    for (int item = warp; item < 7 * 4; item += 16) {
        int nt = item >> 2, cg = item & 3;
        float acc[2][4] = {{0.f,0.f,0.f,0.f},{0.f,0.f,0.f,0.f}};
        for (int ks = 0; ks < 25; ks++) {
            int kb = ks * 8;
            float av[4];
            av[0] = S[(nt * 16 + r)     * 212 + kb + tq];
            av[1] = S[(nt * 16 + r + 8) * 212 + kb + tq];
            av[2] = S[(nt * 16 + r)     * 212 + kb + tq + 4];
            av[3] = S[(nt * 16 + r + 8) * 212 + kb + tq + 4];
            unsigned ahi[4], alo[4];
#pragma unroll
            for (int i = 0; i < 4; i++) {
                ahi[i] = f2tf32(av[i]);
                alo[i] = f2tf32(av[i] - __uint_as_float(ahi[i]));
            }
#pragma unroll
            for (int mt = 0; mt < 2; mt++) {
                int cb = cg * 16 + mt * 8;
                float b0 = Vs[(kb + tq)     * 72 + cb + r];
                float b1 = Vs[(kb + tq + 4) * 72 + cb + r];
                unsigned bhi[2], blo[2];
                bhi[0] = f2tf32(b0); bhi[1] = f2tf32(b1);
                blo[0] = f2tf32(b0 - __uint_as_float(bhi[0]));
                blo[1] = f2tf32(b1 - __uint_as_float(bhi[1]));
                mma_tf32(acc[mt], ahi, bhi);
                mma_tf32(acc[mt], ahi, blo);
                mma_tf32(acc[mt], alo, bhi);
            }
        }
#pragma unroll
        for (int mt = 0; mt < 2; mt++) {
            int c = cg * 16 + mt * 8 + 2 * tq;
            int row = nt * 16 + r;
            if (row < 98)
                *(float2*)(og + (size_t)(q0 + row) * DIMC + c) =
                    make_float2(acc[mt][0], acc[mt][1]);
            if (row + 8 < 98)
                *(float2*)(og + (size_t)(q0 + row + 8) * DIMC + c) =
                    make_float2(acc[mt][2], acc[mt][3]);
        }
    }
}

// ---------------- launch ----------------------------------------------------
extern "C" void kernel_launch(void* const* d_in, const int* in_sizes, int n_in,
                              void* d_out, int out_size)
{
    const float* x     = (const float*)d_in[0];  // [64,196,768]
    const float* Wqkv  = (const float*)d_in[1];  // [768,2304]
    const float* sa    = (const float*)d_in[2];  // [1,12,196,196]
    const float* Wproj = (const float*)d_in[3];  // [768,768]
    const float* bproj = (const float*)d_in[4];  // [768]
    float* out = (float*)d_out;                  // [64,196,768]

    void *p_qkv, *p_ao;
    cudaGetSymbolAddress(&p_qkv, g_qkv);
    cudaGetSymbolAddress(&p_ao, g_ao);
    float* qkv = (float*)p_qkv;
    float* ao  = (float*)p_ao;

    static int smem_set = 0;
    if (!smem_set) {
        cudaFuncSetAttribute(fused_attn_kernel,
                             cudaFuncAttributeMaxDynamicSharedMemorySize,
                             FUSED_SMEM_BYTES);
        smem_set = 1;
    }

    // 1) QKV GEMM: [12544,768] @ [768,2304]  (tf32, 128x128 tile)
    gemm_tf32_kernel<<<dim3(QKV3 / TBN, BN / TBM), 256>>>(x, Wqkv, nullptr, qkv,
                                                          BN, QKV3, DIMC, 0);
    // 2-4) fused scores + softmax(+static_a) + AV
    fused_attn_kernel<<<BATCH * HEADS * 2, 512, FUSED_SMEM_BYTES>>>(qkv, sa, ao);
    // 5) output projection + bias (tf32, 128x128 tile)
    gemm_tf32_kernel<<<dim3(DIMC / TBN, BN / TBM), 256>>>(ao, Wproj, bproj, out,
                                                          BN, DIMC, DIMC, 1);
}

// round 11
// speedup vs baseline: 1.3919x; 1.0942x over previous
#include <cuda_runtime.h>
#include <cuda_bf16.h>
#include <math.h>

#define BATCH 64
#define SEQ   196
#define DIMC  768
#define HEADS 12
#define HD    64
#define QKV3  2304           // 3*DIMC
#define BN    (BATCH*SEQ)    // 12544
#define SCALE 0.125f         // HD^-0.5

// ---------------- scratch (no allocation allowed; __device__ globals) -------
__device__ float g_qkv[(size_t)BATCH * SEQ * QKV3];           // [BN, 2304]
__device__ float g_ao[(size_t)BATCH * SEQ * DIMC];            // [BN, 768]

// ---------------- tf32 helpers ----------------------------------------------
__device__ __forceinline__ unsigned f2tf32(float x) {
    unsigned u;
    asm volatile("cvt.rna.tf32.f32 %0, %1;" : "=r"(u) : "f"(x));
    return u;
}

__device__ __forceinline__ void mma_tf32(float (&d)[4], const unsigned (&a)[4],
                                         const unsigned (&b)[2]) {
    asm volatile(
        "mma.sync.aligned.m16n8k8.row.col.f32.tf32.tf32.f32 "
        "{%0,%1,%2,%3}, {%4,%5,%6,%7}, {%8,%9}, {%0,%1,%2,%3};\n"
        : "+f"(d[0]), "+f"(d[1]), "+f"(d[2]), "+f"(d[3])
        : "r"(a[0]), "r"(a[1]), "r"(a[2]), "r"(a[3]), "r"(b[0]), "r"(b[1]));
}

// ---------------- TF32 GEMM: C[M,N] = A[M,K] @ B[K,N] (+bias) ---------------
// 128x128 block tile, BK=32, 256 threads = 8 warps (4M x 2N), warp tile 32x64.
// (R9 config — best measured: QKV 292us, tensor 50%.)
#define TBM 128
#define TBN 128
#define TBK 32
#define AS_STRIDE 36    // %32==4 -> A frag banks (4r+tq) all distinct
#define BS_STRIDE 136   // %32==8 -> B frag banks (8tq+r) all distinct

__global__ __launch_bounds__(256, 2)
void gemm_tf32_kernel(const float* __restrict__ A, const float* __restrict__ B,
                      const float* __restrict__ bias, float* __restrict__ C,
                      int M, int N, int K, int useBias)
{
    __shared__ unsigned As[TBM * AS_STRIDE];   // [m][k]
    __shared__ unsigned Bs[TBK * BS_STRIDE];   // [k][n]

    const int tid  = threadIdx.x;
    const int lane = tid & 31;
    const int warp = tid >> 5;
    const int r    = lane >> 2;
    const int tq   = lane & 3;
    const int warpM = (warp & 3) * 32;     // 4 warps in M
    const int warpN = (warp >> 2) * 64;    // 2 warps in N, 64 cols each

    const int n0 = blockIdx.x * TBN;
    const int m0 = blockIdx.y * TBM;

    float acc[2][8][4];
#pragma unroll
    for (int i = 0; i < 2; i++)
#pragma unroll
        for (int j = 0; j < 8; j++)
#pragma unroll
            for (int t = 0; t < 4; t++) acc[i][j][t] = 0.f;

    for (int k0 = 0; k0 < K; k0 += TBK) {
#pragma unroll
        for (int i = 0; i < 4; i++) {
            int f   = tid + i * 256;
            int row = f >> 3;
            int kk  = (f & 7) * 4;
            float4 v = *(const float4*)(A + (size_t)(m0 + row) * K + k0 + kk);
            uint4 o;
            o.x = f2tf32(v.x); o.y = f2tf32(v.y);
            o.z = f2tf32(v.z); o.w = f2tf32(v.w);
            *(uint4*)&As[row * AS_STRIDE + kk] = o;
        }
#pragma unroll
        for (int i = 0; i < 4; i++) {
            int f   = tid + i * 256;
            int kk  = f >> 5;
            int nn  = (f & 31) * 4;
            float4 v = *(const float4*)(B + (size_t)(k0 + kk) * N + n0 + nn);
            uint4 o;
            o.x = f2tf32(v.x); o.y = f2tf32(v.y);
            o.z = f2tf32(v.z); o.w = f2tf32(v.w);
            *(uint4*)&Bs[kk * BS_STRIDE + nn] = o;
        }
        __syncthreads();

#pragma unroll
        for (int ks = 0; ks < 4; ks++) {
            int kb = ks * 8;
            unsigned afrag[2][4];
#pragma unroll
            for (int mt = 0; mt < 2; mt++) {
                int rb = warpM + mt * 16;
                afrag[mt][0] = As[(rb + r)     * AS_STRIDE + kb + tq];
                afrag[mt][1] = As[(rb + r + 8) * AS_STRIDE + kb + tq];
                afrag[mt][2] = As[(rb + r)     * AS_STRIDE + kb + tq + 4];
                afrag[mt][3] = As[(rb + r + 8) * AS_STRIDE + kb + tq + 4];
            }
            unsigned bfrag[8][2];
#pragma unroll
            for (int nt = 0; nt < 8; nt++) {
                int cb = warpN + nt * 8;
                bfrag[nt][0] = Bs[(kb + tq)     * BS_STRIDE + cb + r];
                bfrag[nt][1] = Bs[(kb + tq + 4) * BS_STRIDE + cb + r];
            }
#pragma unroll
            for (int mt = 0; mt < 2; mt++)
#pragma unroll
                for (int nt = 0; nt < 8; nt++)
                    mma_tf32(acc[mt][nt], afrag[mt], bfrag[nt]);
        }
        __syncthreads();
    }

#pragma unroll
    for (int mt = 0; mt < 2; mt++) {
#pragma unroll
        for (int nt = 0; nt < 8; nt++) {
            int row = m0 + warpM + mt * 16 + r;
            int col = n0 + warpN + nt * 8 + 2 * tq;
            float2 lo = make_float2(acc[mt][nt][0], acc[mt][nt][1]);
            float2 hi = make_float2(acc[mt][nt][2], acc[mt][nt][3]);
            if (useBias) {
                float2 bv = *(const float2*)(bias + col);
                lo.x += bv.x; lo.y += bv.y;
                hi.x += bv.x; hi.y += bv.y;
            }
            *(float2*)(C + (size_t)row * N + col)       = lo;
            *(float2*)(C + (size_t)(row + 8) * N + col) = hi;
        }
    }
}

// ---------------- fused attention: scores + softmax(+bias) + AV -------------
// One block per (b, h, q-half of 98 rows). 512 threads = 16 warps.
// Pass 2 writes S as tf32 BITS; V stored as tf32 bits at load ->
// pass 3 is pure LDS+MMA (single tf32 mma, no split, no cvt).
#define QS_OFF 0
#define KV_OFF 7616            // 112*68
#define S_OFF  22016           // 7616 + 14400
#define FUSED_SMEM_BYTES (45760 * 4)   // 183040

__global__ __launch_bounds__(512)
void fused_attn_kernel(const float* __restrict__ qkv,
                       const float* __restrict__ sa,
                       float* __restrict__ ao)
{
    extern __shared__ float sm[];
    unsigned* Qs = (unsigned*)(sm + QS_OFF);   // [112][68] (SCALE pre-folded)
    unsigned* Ks = (unsigned*)(sm + KV_OFF);   // [208][68] (pass 1)
    unsigned* Vs = (unsigned*)(sm + KV_OFF);   // [200][72] tf32 bits (pass 3)
    float*    S  = sm + S_OFF;                 // [112][212]
    unsigned* Su = (unsigned*)S;

    const int bid = blockIdx.x;
    const int bh = bid >> 1, qb = bid & 1;
    const int b = bh / HEADS, h = bh % HEADS;
    const int q0 = qb * 98;

    const float* Qg = qkv + (size_t)b * SEQ * QKV3 + h * HD;
    const float* Kg = Qg + DIMC;
    const float* Vg = Qg + 2 * DIMC;

    const int tid  = threadIdx.x;
    const int lane = tid & 31;
    const int warp = tid >> 5;
    const int r    = lane >> 2;
    const int tq   = lane & 3;

    // ---- load Q (tf32, pre-scaled by SCALE: exact power of two)
    for (int i = tid; i < 112 * 16; i += 512) {
        int row = i >> 4, c4 = (i & 15) * 4;
        float4 v = make_float4(0.f, 0.f, 0.f, 0.f);
        if (row < 98) v = *(const float4*)(Qg + (size_t)(q0 + row) * QKV3 + c4);
        unsigned* p = &Qs[row * 68 + c4];
        p[0] = f2tf32(v.x * SCALE); p[1] = f2tf32(v.y * SCALE);
        p[2] = f2tf32(v.z * SCALE); p[3] = f2tf32(v.w * SCALE);
    }
    // ---- load K (tf32), rows >= 196 zeroed
    for (int i = tid; i < 208 * 16; i += 512) {
        int row = i >> 4, c4 = (i & 15) * 4;
        float4 v = make_float4(0.f, 0.f, 0.f, 0.f);
        if (row < SEQ) v = *(const float4*)(Kg + (size_t)row * QKV3 + c4);
        unsigned* p = &Ks[row * 68 + c4];
        p[0] = f2tf32(v.x); p[1] = f2tf32(v.y);
        p[2] = f2tf32(v.z); p[3] = f2tf32(v.w);
    }
    __syncthreads();

    // ---- pass 1: S[112][208] = (Q*SCALE) @ K^T  (fp32 logits in S)
    for (int item = warp; item < 7 * 13; item += 16) {
        int nt = item / 13, mg = item % 13;
        float acc[2][4] = {{0.f,0.f,0.f,0.f},{0.f,0.f,0.f,0.f}};
#pragma unroll
        for (int ks = 0; ks < 8; ks++) {
            int kb = ks * 8;
            unsigned af[4];
            af[0] = Qs[(nt * 16 + r)     * 68 + kb + tq];
            af[1] = Qs[(nt * 16 + r + 8) * 68 + kb + tq];
            af[2] = Qs[(nt * 16 + r)     * 68 + kb + tq + 4];
            af[3] = Qs[(nt * 16 + r + 8) * 68 + kb + tq + 4];
#pragma unroll
            for (int mt = 0; mt < 2; mt++) {
                int cb = mg * 16 + mt * 8;
                unsigned bf[2];
                bf[0] = Ks[(cb + r) * 68 + kb + tq];
                bf[1] = Ks[(cb + r) * 68 + kb + tq + 4];
                mma_tf32(acc[mt], af, bf);
            }
        }
#pragma unroll
        for (int mt = 0; mt < 2; mt++) {
            int c = mg * 16 + mt * 8 + 2 * tq;
            int row = nt * 16 + r;
            S[row * 212 + c]           = acc[mt][0];
            S[row * 212 + c + 1]       = acc[mt][1];
            S[(row + 8) * 212 + c]     = acc[mt][2];
            S[(row + 8) * 212 + c + 1] = acc[mt][3];
        }
    }
    __syncthreads();

    // ---- load V as tf32 bits, rows >= 196 zeroed
    for (int i = tid; i < 200 * 16; i += 512) {
        int row = i >> 4, c4 = (i & 15) * 4;
        float4 v = make_float4(0.f, 0.f, 0.f, 0.f);
        if (row < SEQ) v = *(const float4*)(Vg + (size_t)row * QKV3 + c4);
        unsigned* p = &Vs[row * 72 + c4];
        p[0] = f2tf32(v.x); p[1] = f2tf32(v.y);
        p[2] = f2tf32(v.z); p[3] = f2tf32(v.w);
    }

    // ---- pass 2: softmax + static_a, write back as tf32 BITS
    for (int row = warp; row < 98; row += 16) {
        float* Sr = S + row * 212;
        unsigned* Sru = (unsigned*)Sr;
        float vals[7];
        float mx = -INFINITY;
#pragma unroll
        for (int j = 0; j < 7; j++) {
            int c = lane + 32 * j;
            vals[j] = (c < SEQ) ? Sr[c] : -INFINITY;
            mx = fmaxf(mx, vals[j]);
        }
#pragma unroll
        for (int s = 16; s; s >>= 1) mx = fmaxf(mx, __shfl_xor_sync(0xffffffffu, mx, s));
        float sum = 0.f;
#pragma unroll
        for (int j = 0; j < 7; j++) { vals[j] = __expf(vals[j] - mx); sum += vals[j]; }
#pragma unroll
        for (int s = 16; s; s >>= 1) sum += __shfl_xor_sync(0xffffffffu, sum, s);
        float inv = 1.f / sum;
        const float* ar = sa + ((size_t)h * SEQ + q0 + row) * SEQ;
#pragma unroll
        for (int j = 0; j < 7; j++) {
            int c = lane + 32 * j;
            if (c < SEQ) Sru[c] = f2tf32(vals[j] * inv + ar[c]);
            else if (c < 208) Sru[c] = 0u;   // pad cols: exact zero
        }
    }
    __syncthreads();

    // ---- pass 3: out = S(98x196) @ V(196x64), single tf32 mma (operands
    //      pre-converted; error hidden under the QKV tf32 term)
    float* og = ao + (size_t)b * SEQ * DIMC + h * HD;
    for (int item = warp; item < 7 * 4; item += 16) {
        int nt = item >> 2, cg = item & 3;
        float acc[2][4] = {{0.f,0.f,0.f,0.f},{0.f,0.f,0.f,0.f}};
#pragma unroll
        for (int ks = 0; ks < 25; ks++) {
            int kb = ks * 8;
            unsigned af[4];
            af[0] = Su[(nt * 16 + r)     * 212 + kb + tq];
            af[1] = Su[(nt * 16 + r + 8) * 212 + kb + tq];
            af[2] = Su[(nt * 16 + r)     * 212 + kb + tq + 4];
            af[3] = Su[(nt * 16 + r + 8) * 212 + kb + tq + 4];
#pragma unroll
            for (int mt = 0; mt < 2; mt++) {
                int cb = cg * 16 + mt * 8;
                unsigned bf[2];
                bf[0] = Vs[(kb + tq)     * 72 + cb + r];
                bf[1] = Vs[(kb + tq + 4) * 72 + cb + r];
                mma_tf32(acc[mt], af, bf);
            }
        }
#pragma unroll
        for (int mt = 0; mt < 2; mt++) {
            int c = cg * 16 + mt * 8 + 2 * tq;
            int row = nt * 16 + r;
            if (row < 98)
                *(float2*)(og + (size_t)(q0 + row) * DIMC + c) =
                    make_float2(acc[mt][0], acc[mt][1]);
            if (row + 8 < 98)
                *(float2*)(og + (size_t)(q0 + row + 8) * DIMC + c) =
                    make_float2(acc[mt][2], acc[mt][3]);
        }
    }
}

// ---------------- launch ----------------------------------------------------
extern "C" void kernel_launch(void* const* d_in, const int* in_sizes, int n_in,
                              void* d_out, int out_size)
{
    const float* x     = (const float*)d_in[0];  // [64,196,768]
    const float* Wqkv  = (const float*)d_in[1];  // [768,2304]
    const float* sa    = (const float*)d_in[2];  // [1,12,196,196]
    const float* Wproj = (const float*)d_in[3];  // [768,768]
    const float* bproj = (const float*)d_in[4];  // [768]
    float* out = (float*)d_out;                  // [64,196,768]

    void *p_qkv, *p_ao;
    cudaGetSymbolAddress(&p_qkv, g_qkv);
    cudaGetSymbolAddress(&p_ao, g_ao);
    float* qkv = (float*)p_qkv;
    float* ao  = (float*)p_ao;

    static int smem_set = 0;
    if (!smem_set) {
        cudaFuncSetAttribute(fused_attn_kernel,
                             cudaFuncAttributeMaxDynamicSharedMemorySize,
                             FUSED_SMEM_BYTES);
        smem_set = 1;
    }

    // 1) QKV GEMM: [12544,768] @ [768,2304]  (tf32, 128x128 tile)
    gemm_tf32_kernel<<<dim3(QKV3 / TBN, BN / TBM), 256>>>(x, Wqkv, nullptr, qkv,
                                                          BN, QKV3, DIMC, 0);
    // 2-4) fused scores + softmax(+static_a) + AV (1xTF32 AV)
    fused_attn_kernel<<<BATCH * HEADS * 2, 512, FUSED_SMEM_BYTES>>>(qkv, sa, ao);
    // 5) output projection + bias (tf32, 128x128 tile)
    gemm_tf32_kernel<<<dim3(DIMC / TBN, BN / TBM), 256>>>(ao, Wproj, bproj, out,
                                                          BN, DIMC, DIMC, 1);
}

// round 13
// speedup vs baseline: 1.4087x; 1.0121x over previous
#include <cuda_runtime.h>
#include <cuda_bf16.h>
#include <math.h>

#define BATCH 64
#define SEQ   196
#define DIMC  768
#define HEADS 12
#define HD    64
#define QKV3  2304           // 3*DIMC
#define BN    (BATCH*SEQ)    // 12544
#define SCALE 0.125f         // HD^-0.5
#define NBLK  (BATCH*HEADS*2)  // 1536 (b,h,q-half)

// ---------------- scratch (no allocation allowed; __device__ globals) -------
__device__ float    g_qkv[(size_t)BATCH * SEQ * QKV3];       // [BN, 2304]
__device__ float    g_ao[(size_t)BATCH * SEQ * DIMC];        // [BN, 768]
__device__ unsigned g_S[(size_t)NBLK * 112 * 208];           // tf32 probs+bias

// ---------------- tf32 helpers ----------------------------------------------
__device__ __forceinline__ unsigned f2tf32(float x) {
    unsigned u;
    asm volatile("cvt.rna.tf32.f32 %0, %1;" : "=r"(u) : "f"(x));
    return u;
}

__device__ __forceinline__ void mma_tf32(float (&d)[4], const unsigned (&a)[4],
                                         const unsigned (&b)[2]) {
    asm volatile(
        "mma.sync.aligned.m16n8k8.row.col.f32.tf32.tf32.f32 "
        "{%0,%1,%2,%3}, {%4,%5,%6,%7}, {%8,%9}, {%0,%1,%2,%3};\n"
        : "+f"(d[0]), "+f"(d[1]), "+f"(d[2]), "+f"(d[3])
        : "r"(a[0]), "r"(a[1]), "r"(a[2]), "r"(a[3]), "r"(b[0]), "r"(b[1]));
}

// ---------------- TF32 GEMM (R9/R11 config — unchanged) ----------------------
#define TBM 128
#define TBN 128
#define TBK 32
#define AS_STRIDE 36
#define BS_STRIDE 136

__global__ __launch_bounds__(256, 2)
void gemm_tf32_kernel(const float* __restrict__ A, const float* __restrict__ B,
                      const float* __restrict__ bias, float* __restrict__ C,
                      int M, int N, int K, int useBias)
{
    __shared__ unsigned As[TBM * AS_STRIDE];
    __shared__ unsigned Bs[TBK * BS_STRIDE];

    const int tid  = threadIdx.x;
    const int lane = tid & 31;
    const int warp = tid >> 5;
    const int r    = lane >> 2;
    const int tq   = lane & 3;
    const int warpM = (warp & 3) * 32;
    const int warpN = (warp >> 2) * 64;

    const int n0 = blockIdx.x * TBN;
    const int m0 = blockIdx.y * TBM;

    float acc[2][8][4];
#pragma unroll
    for (int i = 0; i < 2; i++)
#pragma unroll
        for (int j = 0; j < 8; j++)
#pragma unroll
            for (int t = 0; t < 4; t++) acc[i][j][t] = 0.f;

    for (int k0 = 0; k0 < K; k0 += TBK) {
#pragma unroll
        for (int i = 0; i < 4; i++) {
            int f   = tid + i * 256;
            int row = f >> 3;
            int kk  = (f & 7) * 4;
            float4 v = *(const float4*)(A + (size_t)(m0 + row) * K + k0 + kk);
            uint4 o;
            o.x = f2tf32(v.x); o.y = f2tf32(v.y);
            o.z = f2tf32(v.z); o.w = f2tf32(v.w);
            *(uint4*)&As[row * AS_STRIDE + kk] = o;
        }
#pragma unroll
        for (int i = 0; i < 4; i++) {
            int f   = tid + i * 256;
            int kk  = f >> 5;
            int nn  = (f & 31) * 4;
            float4 v = *(const float4*)(B + (size_t)(k0 + kk) * N + n0 + nn);
            uint4 o;
            o.x = f2tf32(v.x); o.y = f2tf32(v.y);
            o.z = f2tf32(v.z); o.w = f2tf32(v.w);
            *(uint4*)&Bs[kk * BS_STRIDE + nn] = o;
        }
        __syncthreads();

#pragma unroll
        for (int ks = 0; ks < 4; ks++) {
            int kb = ks * 8;
            unsigned afrag[2][4];
#pragma unroll
            for (int mt = 0; mt < 2; mt++) {
                int rb = warpM + mt * 16;
                afrag[mt][0] = As[(rb + r)     * AS_STRIDE + kb + tq];
                afrag[mt][1] = As[(rb + r + 8) * AS_STRIDE + kb + tq];
                afrag[mt][2] = As[(rb + r)     * AS_STRIDE + kb + tq + 4];
                afrag[mt][3] = As[(rb + r + 8) * AS_STRIDE + kb + tq + 4];
            }
            unsigned bfrag[8][2];
#pragma unroll
            for (int nt = 0; nt < 8; nt++) {
                int cb = warpN + nt * 8;
                bfrag[nt][0] = Bs[(kb + tq)     * BS_STRIDE + cb + r];
                bfrag[nt][1] = Bs[(kb + tq + 4) * BS_STRIDE + cb + r];
            }
#pragma unroll
            for (int mt = 0; mt < 2; mt++)
#pragma unroll
                for (int nt = 0; nt < 8; nt++)
                    mma_tf32(acc[mt][nt], afrag[mt], bfrag[nt]);
        }
        __syncthreads();
    }

#pragma unroll
    for (int mt = 0; mt < 2; mt++) {
#pragma unroll
        for (int nt = 0; nt < 8; nt++) {
            int row = m0 + warpM + mt * 16 + r;
            int col = n0 + warpN + nt * 8 + 2 * tq;
            float2 lo = make_float2(acc[mt][nt][0], acc[mt][nt][1]);
            float2 hi = make_float2(acc[mt][nt][2], acc[mt][nt][3]);
            if (useBias) {
                float2 bv = *(const float2*)(bias + col);
                lo.x += bv.x; lo.y += bv.y;
                hi.x += bv.x; hi.y += bv.y;
            }
            *(float2*)(C + (size_t)row * N + col)       = lo;
            *(float2*)(C + (size_t)(row + 8) * N + col) = hi;
        }
    }
}

// ---------------- K1: scores + register softmax + bias -> tf32 S (gmem) -----
// One block per (b,h,qhalf). 224 threads = 7 warps; warp w owns S rows
// [w*16, w*16+16) x all 208 cols in registers (acc[13][2][4]).
__global__ __launch_bounds__(224, 2)
void scores_softmax_kernel(const float* __restrict__ qkv,
                           const float* __restrict__ sa,
                           unsigned* __restrict__ Sg)
{
    __shared__ unsigned Qs[112 * 68];   // SCALE pre-folded, rows>=98 zero
    __shared__ unsigned Ks[208 * 68];   // rows>=196 zero

    const int bid = blockIdx.x;
    const int bh = bid >> 1, qb = bid & 1;
    const int b = bh / HEADS, h = bh % HEADS;
    const int q0 = qb * 98;

    const float* Qg = qkv + (size_t)b * SEQ * QKV3 + h * HD;
    const float* Kg = Qg + DIMC;

    const int tid  = threadIdx.x;
    const int lane = tid & 31;
    const int warp = tid >> 5;
    const int r    = lane >> 2;
    const int tq   = lane & 3;

    for (int i = tid; i < 112 * 16; i += 224) {
        int row = i >> 4, c4 = (i & 15) * 4;
        float4 v = make_float4(0.f, 0.f, 0.f, 0.f);
        if (row < 98) v = *(const float4*)(Qg + (size_t)(q0 + row) * QKV3 + c4);
        uint4 o;
        o.x = f2tf32(v.x * SCALE); o.y = f2tf32(v.y * SCALE);
        o.z = f2tf32(v.z * SCALE); o.w = f2tf32(v.w * SCALE);
        *(uint4*)&Qs[row * 68 + c4] = o;
    }
    for (int i = tid; i < 208 * 16; i += 224) {
        int row = i >> 4, c4 = (i & 15) * 4;
        float4 v = make_float4(0.f, 0.f, 0.f, 0.f);
        if (row < SEQ) v = *(const float4*)(Kg + (size_t)row * QKV3 + c4);
        uint4 o;
        o.x = f2tf32(v.x); o.y = f2tf32(v.y);
        o.z = f2tf32(v.z); o.w = f2tf32(v.w);
        *(uint4*)&Ks[row * 68 + c4] = o;
    }
    __syncthreads();

    // ---- scores: warp strip 16 rows x 208 cols, K-dim 64 (8 k-steps)
    float acc[13][2][4];
#pragma unroll
    for (int mg = 0; mg < 13; mg++)
#pragma unroll
        for (int mt = 0; mt < 2; mt++)
#pragma unroll
            for (int t = 0; t < 4; t++) acc[mg][mt][t] = 0.f;

    const int rb = warp * 16;
#pragma unroll
    for (int ks = 0; ks < 8; ks++) {
        int kb = ks * 8;
        unsigned af[4];
        af[0] = Qs[(rb + r)     * 68 + kb + tq];
        af[1] = Qs[(rb + r + 8) * 68 + kb + tq];
        af[2] = Qs[(rb + r)     * 68 + kb + tq + 4];
        af[3] = Qs[(rb + r + 8) * 68 + kb + tq + 4];
#pragma unroll
        for (int mg = 0; mg < 13; mg++)
#pragma unroll
            for (int mt = 0; mt < 2; mt++) {
                int cb = mg * 16 + mt * 8;
                unsigned bf[2];
                bf[0] = Ks[(cb + r) * 68 + kb + tq];
                bf[1] = Ks[(cb + r) * 68 + kb + tq + 4];
                mma_tf32(acc[mg][mt], af, bf);
            }
    }

    // ---- register softmax over each row (the 4 lanes sharing r hold a row)
    float mx0 = -INFINITY, mx1 = -INFINITY;
#pragma unroll
    for (int mg = 0; mg < 13; mg++)
#pragma unroll
        for (int mt = 0; mt < 2; mt++)
#pragma unroll
            for (int j = 0; j < 2; j++) {
                bool valid = (mg < 12) || (mt == 0 && (2 * tq + j) < 4);
                if (valid) {
                    mx0 = fmaxf(mx0, acc[mg][mt][j]);
                    mx1 = fmaxf(mx1, acc[mg][mt][2 + j]);
                }
            }
    mx0 = fmaxf(mx0, __shfl_xor_sync(0xffffffffu, mx0, 1));
    mx0 = fmaxf(mx0, __shfl_xor_sync(0xffffffffu, mx0, 2));
    mx1 = fmaxf(mx1, __shfl_xor_sync(0xffffffffu, mx1, 1));
    mx1 = fmaxf(mx1, __shfl_xor_sync(0xffffffffu, mx1, 2));

    float sum0 = 0.f, sum1 = 0.f;
#pragma unroll
    for (int mg = 0; mg < 13; mg++)
#pragma unroll
        for (int mt = 0; mt < 2; mt++)
#pragma unroll
            for (int j = 0; j < 2; j++) {
                bool valid = (mg < 12) || (mt == 0 && (2 * tq + j) < 4);
                float e0 = valid ? __expf(acc[mg][mt][j]     - mx0) : 0.f;
                float e1 = valid ? __expf(acc[mg][mt][2 + j] - mx1) : 0.f;
                acc[mg][mt][j]     = e0;
                acc[mg][mt][2 + j] = e1;
                sum0 += e0;
                sum1 += e1;
            }
    sum0 += __shfl_xor_sync(0xffffffffu, sum0, 1);
    sum0 += __shfl_xor_sync(0xffffffffu, sum0, 2);
    sum1 += __shfl_xor_sync(0xffffffffu, sum1, 1);
    sum1 += __shfl_xor_sync(0xffffffffu, sum1, 2);
    const float inv0 = 1.f / sum0;
    const float inv1 = 1.f / sum1;

    // ---- add static_a, convert to tf32 bits, store to gmem
    const int row0 = rb + r, row1 = rb + r + 8;
    const float* ar0 = sa + ((size_t)h * SEQ + q0 + row0) * SEQ;
    const float* ar1 = sa + ((size_t)h * SEQ + q0 + row1) * SEQ;
    unsigned* S0 = Sg + ((size_t)bid * 112 + row0) * 208;
    unsigned* S1 = Sg + ((size_t)bid * 112 + row1) * 208;
    const bool rOk0 = row0 < 98, rOk1 = row1 < 98;
#pragma unroll
    for (int mg = 0; mg < 13; mg++)
#pragma unroll
        for (int mt = 0; mt < 2; mt++) {
            int c = mg * 16 + mt * 8 + 2 * tq;
            uint2 o0, o1;
#pragma unroll
            for (int j = 0; j < 2; j++) {
                bool valid = (mg < 12) || (mt == 0 && (2 * tq + j) < 4);
                float a0 = (valid && rOk0) ? ar0[c + j] : 0.f;
                float a1 = (valid && rOk1) ? ar1[c + j] : 0.f;
                float v0 = valid ? acc[mg][mt][j]     * inv0 + a0 : 0.f;
                float v1 = valid ? acc[mg][mt][2 + j] * inv1 + a1 : 0.f;
                ((unsigned*)&o0)[j] = f2tf32(v0);
                ((unsigned*)&o1)[j] = f2tf32(v1);
            }
            *(uint2*)(S0 + c) = o0;
            *(uint2*)(S1 + c) = o1;
        }
}

// ---------------- K2: AV GEMM  out[112x64] = S[112x208] @ V[208x64] ---------
// One block per (b,h,qhalf). 224 threads = 7 warps; warp w -> rows [w*16,+16).
#define K2_AS 20    // S tile stride (%32==20 -> banks 20r+tq distinct)
#define K2_VS 72    // V tile stride (%32==8  -> banks 8tq+r distinct)

__global__ __launch_bounds__(224)
void av_kernel(const unsigned* __restrict__ Sg, const float* __restrict__ qkv,
               float* __restrict__ ao)
{
    __shared__ unsigned As[112 * K2_AS];   // S tile [112][16]
    __shared__ unsigned Vs[16 * K2_VS];    // V tile [16][64] tf32

    const int bid = blockIdx.x;
    const int bh = bid >> 1, qb = bid & 1;
    const int b = bh / HEADS, h = bh % HEADS;
    const int q0 = qb * 98;

    const float* Vg = qkv + (size_t)b * SEQ * QKV3 + 2 * DIMC + h * HD;
    const unsigned* Sb = Sg + (size_t)bid * 112 * 208;

    const int tid  = threadIdx.x;
    const int lane = tid & 31;
    const int warp = tid >> 5;
    const int r    = lane >> 2;
    const int tq   = lane & 3;
    const int rb   = warp * 16;

    float acc[8][4];
#pragma unroll
    for (int nt = 0; nt < 8; nt++)
#pragma unroll
        for (int t = 0; t < 4; t++) acc[nt][t] = 0.f;

    for (int kt = 0; kt < 13; kt++) {
        const int k0 = kt * 16;
        // S tile: 112 rows x 16 k (tf32 bits, direct copy), 448 items
        for (int i = tid; i < 112 * 4; i += 224) {
            int row = i >> 2, kc = (i & 3) * 4;
            uint4 v = *(const uint4*)(Sb + (size_t)row * 208 + k0 + kc);
            *(uint4*)&As[row * K2_AS + kc] = v;
        }
        // V tile: 16 k-rows x 64 cols = 256 items > 224 threads -> STRIDED
        for (int i = tid; i < 16 * 16; i += 224) {
            int k = i >> 4, c4 = (i & 15) * 4;
            float4 v = make_float4(0.f, 0.f, 0.f, 0.f);
            if (k0 + k < SEQ) v = *(const float4*)(Vg + (size_t)(k0 + k) * QKV3 + c4);
            uint4 o;
            o.x = f2tf32(v.x); o.y = f2tf32(v.y);
            o.z = f2tf32(v.z); o.w = f2tf32(v.w);
            *(uint4*)&Vs[k * K2_VS + c4] = o;
        }
        __syncthreads();

#pragma unroll
        for (int ks = 0; ks < 2; ks++) {
            int kb = ks * 8;
            unsigned af[4];
            af[0] = As[(rb + r)     * K2_AS + kb + tq];
            af[1] = As[(rb + r + 8) * K2_AS + kb + tq];
            af[2] = As[(rb + r)     * K2_AS + kb + tq + 4];
            af[3] = As[(rb + r + 8) * K2_AS + kb + tq + 4];
#pragma unroll
            for (int nt = 0; nt < 8; nt++) {
                unsigned bf[2];
                bf[0] = Vs[(kb + tq)     * K2_VS + nt * 8 + r];
                bf[1] = Vs[(kb + tq + 4) * K2_VS + nt * 8 + r];
                mma_tf32(acc[nt], af, bf);
            }
        }
        __syncthreads();
    }

    float* og = ao + (size_t)b * SEQ * DIMC + h * HD;
    const int row0 = rb + r, row1 = rb + r + 8;
#pragma unroll
    for (int nt = 0; nt < 8; nt++) {
        int c = nt * 8 + 2 * tq;
        if (row0 < 98)
            *(float2*)(og + (size_t)(q0 + row0) * DIMC + c) =
                make_float2(acc[nt][0], acc[nt][1]);
        if (row1 < 98)
            *(float2*)(og + (size_t)(q0 + row1) * DIMC + c) =
                make_float2(acc[nt][2], acc[nt][3]);
    }
}

// ---------------- launch ----------------------------------------------------
extern "C" void kernel_launch(void* const* d_in, const int* in_sizes, int n_in,
                              void* d_out, int out_size)
{
    const float* x     = (const float*)d_in[0];  // [64,196,768]
    const float* Wqkv  = (const float*)d_in[1];  // [768,2304]
    const float* sa    = (const float*)d_in[2];  // [1,12,196,196]
    const float* Wproj = (const float*)d_in[3];  // [768,768]
    const float* bproj = (const float*)d_in[4];  // [768]
    float* out = (float*)d_out;                  // [64,196,768]

    void *p_qkv, *p_ao, *p_S;
    cudaGetSymbolAddress(&p_qkv, g_qkv);
    cudaGetSymbolAddress(&p_ao, g_ao);
    cudaGetSymbolAddress(&p_S, g_S);
    float*    qkv = (float*)p_qkv;
    float*    ao  = (float*)p_ao;
    unsigned* Sg  = (unsigned*)p_S;

    // 1) QKV GEMM
    gemm_tf32_kernel<<<dim3(QKV3 / TBN, BN / TBM), 256>>>(x, Wqkv, nullptr, qkv,
                                                          BN, QKV3, DIMC, 0);
    // 2) scores + register softmax + bias -> tf32 S
    scores_softmax_kernel<<<NBLK, 224>>>(qkv, sa, Sg);
    // 3) AV
    av_kernel<<<NBLK, 224>>>(Sg, qkv, ao);
    // 4) output projection + bias
    gemm_tf32_kernel<<<dim3(DIMC / TBN, BN / TBM), 256>>>(ao, Wproj, bproj, out,
                                                          BN, DIMC, DIMC, 1);
}

// round 14
// speedup vs baseline: 1.4965x; 1.0623x over previous
#include <cuda_runtime.h>
#include <cuda_bf16.h>
#include <math.h>

#define BATCH 64
#define SEQ   196
#define DIMC  768
#define HEADS 12
#define HD    64
#define QKV3  2304           // 3*DIMC
#define BN    (BATCH*SEQ)    // 12544
#define SCALE 0.125f         // HD^-0.5
#define NBLK  (BATCH*HEADS*2)  // 1536 (b,h,q-half)

// ---------------- scratch (no allocation allowed; __device__ globals) -------
__device__ float g_qkv[(size_t)BATCH * SEQ * QKV3];          // [BN, 2304]
__device__ float g_ao[(size_t)BATCH * SEQ * DIMC];           // [BN, 768]

// ---------------- tf32 helpers ----------------------------------------------
__device__ __forceinline__ unsigned f2tf32(float x) {
    unsigned u;
    asm volatile("cvt.rna.tf32.f32 %0, %1;" : "=r"(u) : "f"(x));
    return u;
}

__device__ __forceinline__ void mma_tf32(float (&d)[4], const unsigned (&a)[4],
                                         const unsigned (&b)[2]) {
    asm volatile(
        "mma.sync.aligned.m16n8k8.row.col.f32.tf32.tf32.f32 "
        "{%0,%1,%2,%3}, {%4,%5,%6,%7}, {%8,%9}, {%0,%1,%2,%3};\n"
        : "+f"(d[0]), "+f"(d[1]), "+f"(d[2]), "+f"(d[3])
        : "r"(a[0]), "r"(a[1]), "r"(a[2]), "r"(a[3]), "r"(b[0]), "r"(b[1]));
}

// ---------------- TF32 GEMM (R9/R11 config — unchanged) ----------------------
#define TBM 128
#define TBN 128
#define TBK 32
#define AS_STRIDE 36
#define BS_STRIDE 136

__global__ __launch_bounds__(256, 2)
void gemm_tf32_kernel(const float* __restrict__ A, const float* __restrict__ B,
                      const float* __restrict__ bias, float* __restrict__ C,
                      int M, int N, int K, int useBias)
{
    __shared__ unsigned As[TBM * AS_STRIDE];
    __shared__ unsigned Bs[TBK * BS_STRIDE];

    const int tid  = threadIdx.x;
    const int lane = tid & 31;
    const int warp = tid >> 5;
    const int r    = lane >> 2;
    const int tq   = lane & 3;
    const int warpM = (warp & 3) * 32;
    const int warpN = (warp >> 2) * 64;

    const int n0 = blockIdx.x * TBN;
    const int m0 = blockIdx.y * TBM;

    float acc[2][8][4];
#pragma unroll
    for (int i = 0; i < 2; i++)
#pragma unroll
        for (int j = 0; j < 8; j++)
#pragma unroll
            for (int t = 0; t < 4; t++) acc[i][j][t] = 0.f;

    for (int k0 = 0; k0 < K; k0 += TBK) {
#pragma unroll
        for (int i = 0; i < 4; i++) {
            int f   = tid + i * 256;
            int row = f >> 3;
            int kk  = (f & 7) * 4;
            float4 v = *(const float4*)(A + (size_t)(m0 + row) * K + k0 + kk);
            uint4 o;
            o.x = f2tf32(v.x); o.y = f2tf32(v.y);
            o.z = f2tf32(v.z); o.w = f2tf32(v.w);
            *(uint4*)&As[row * AS_STRIDE + kk] = o;
        }
#pragma unroll
        for (int i = 0; i < 4; i++) {
            int f   = tid + i * 256;
            int kk  = f >> 5;
            int nn  = (f & 31) * 4;
            float4 v = *(const float4*)(B + (size_t)(k0 + kk) * N + n0 + nn);
            uint4 o;
            o.x = f2tf32(v.x); o.y = f2tf32(v.y);
            o.z = f2tf32(v.z); o.w = f2tf32(v.w);
            *(uint4*)&Bs[kk * BS_STRIDE + nn] = o;
        }
        __syncthreads();

#pragma unroll
        for (int ks = 0; ks < 4; ks++) {
            int kb = ks * 8;
            unsigned afrag[2][4];
#pragma unroll
            for (int mt = 0; mt < 2; mt++) {
                int rb = warpM + mt * 16;
                afrag[mt][0] = As[(rb + r)     * AS_STRIDE + kb + tq];
                afrag[mt][1] = As[(rb + r + 8) * AS_STRIDE + kb + tq];
                afrag[mt][2] = As[(rb + r)     * AS_STRIDE + kb + tq + 4];
                afrag[mt][3] = As[(rb + r + 8) * AS_STRIDE + kb + tq + 4];
            }
            unsigned bfrag[8][2];
#pragma unroll
            for (int nt = 0; nt < 8; nt++) {
                int cb = warpN + nt * 8;
                bfrag[nt][0] = Bs[(kb + tq)     * BS_STRIDE + cb + r];
                bfrag[nt][1] = Bs[(kb + tq + 4) * BS_STRIDE + cb + r];
            }
#pragma unroll
            for (int mt = 0; mt < 2; mt++)
#pragma unroll
                for (int nt = 0; nt < 8; nt++)
                    mma_tf32(acc[mt][nt], afrag[mt], bfrag[nt]);
        }
        __syncthreads();
    }

#pragma unroll
    for (int mt = 0; mt < 2; mt++) {
#pragma unroll
        for (int nt = 0; nt < 8; nt++) {
            int row = m0 + warpM + mt * 16 + r;
            int col = n0 + warpN + nt * 8 + 2 * tq;
            float2 lo = make_float2(acc[mt][nt][0], acc[mt][nt][1]);
            float2 hi = make_float2(acc[mt][nt][2], acc[mt][nt][3]);
            if (useBias) {
                float2 bv = *(const float2*)(bias + col);
                lo.x += bv.x; lo.y += bv.y;
                hi.x += bv.x; hi.y += bv.y;
            }
            *(float2*)(C + (size_t)row * N + col)       = lo;
            *(float2*)(C + (size_t)(row + 8) * N + col) = hi;
        }
    }
}

// ---------------- fused attention: scores + reg softmax + bias + AV ---------
// One block per (b,h,qhalf). 224 threads = 7 warps; warp w owns rows
// [w*16, w*16+16). S never leaves registers: after softmax+bias, each P
// block (C-frag layout) is converted to A-frag layout via quad shuffles and
// fed straight into the AV mma against V fragments in smem.
// Dynamic smem: Qs[112][68] tf32 | KV union: K [208][68] then V [208][72]
#define FA_KV_OFF 7616                            // words (112*68)
#define FA_SMEM_WORDS (FA_KV_OFF + 208 * 72)      // 22592
#define FA_SMEM_BYTES (FA_SMEM_WORDS * 4)         // 90368

__global__ __launch_bounds__(224, 2)
void attn_fused_kernel(const float* __restrict__ qkv,
                       const float* __restrict__ sa,
                       float* __restrict__ ao)
{
    extern __shared__ unsigned smu[];
    unsigned* Qs = smu;                 // [112][68], SCALE pre-folded
    unsigned* Ks = smu + FA_KV_OFF;     // [208][68] (scores phase)
    unsigned* Vs = smu + FA_KV_OFF;     // [208][72] tf32 (AV phase)

    const int bid = blockIdx.x;
    const int bh = bid >> 1, qb = bid & 1;
    const int b = bh / HEADS, h = bh % HEADS;
    const int q0 = qb * 98;

    const float* Qg = qkv + (size_t)b * SEQ * QKV3 + h * HD;
    const float* Kg = Qg + DIMC;
    const float* Vg = Qg + 2 * DIMC;

    const int tid  = threadIdx.x;
    const int lane = tid & 31;
    const int warp = tid >> 5;
    const int r    = lane >> 2;
    const int tq   = lane & 3;

    // ---- load Q (tf32, pre-scaled), rows >= 98 zeroed
    for (int i = tid; i < 112 * 16; i += 224) {
        int row = i >> 4, c4 = (i & 15) * 4;
        float4 v = make_float4(0.f, 0.f, 0.f, 0.f);
        if (row < 98) v = *(const float4*)(Qg + (size_t)(q0 + row) * QKV3 + c4);
        uint4 o;
        o.x = f2tf32(v.x * SCALE); o.y = f2tf32(v.y * SCALE);
        o.z = f2tf32(v.z * SCALE); o.w = f2tf32(v.w * SCALE);
        *(uint4*)&Qs[row * 68 + c4] = o;
    }
    // ---- load K (tf32), rows >= 196 zeroed
    for (int i = tid; i < 208 * 16; i += 224) {
        int row = i >> 4, c4 = (i & 15) * 4;
        float4 v = make_float4(0.f, 0.f, 0.f, 0.f);
        if (row < SEQ) v = *(const float4*)(Kg + (size_t)row * QKV3 + c4);
        uint4 o;
        o.x = f2tf32(v.x); o.y = f2tf32(v.y);
        o.z = f2tf32(v.z); o.w = f2tf32(v.w);
        *(uint4*)&Ks[row * 68 + c4] = o;
    }
    __syncthreads();

    // ---- scores: warp strip 16 rows x 208 cols, K-dim 64 (8 k-steps)
    float acc[13][2][4];
#pragma unroll
    for (int mg = 0; mg < 13; mg++)
#pragma unroll
        for (int mt = 0; mt < 2; mt++)
#pragma unroll
            for (int t = 0; t < 4; t++) acc[mg][mt][t] = 0.f;

    const int rb = warp * 16;
#pragma unroll
    for (int ks = 0; ks < 8; ks++) {
        int kb = ks * 8;
        unsigned af[4];
        af[0] = Qs[(rb + r)     * 68 + kb + tq];
        af[1] = Qs[(rb + r + 8) * 68 + kb + tq];
        af[2] = Qs[(rb + r)     * 68 + kb + tq + 4];
        af[3] = Qs[(rb + r + 8) * 68 + kb + tq + 4];
#pragma unroll
        for (int mg = 0; mg < 13; mg++)
#pragma unroll
            for (int mt = 0; mt < 2; mt++) {
                int cb = mg * 16 + mt * 8;
                unsigned bf[2];
                bf[0] = Ks[(cb + r) * 68 + kb + tq];
                bf[1] = Ks[(cb + r) * 68 + kb + tq + 4];
                mma_tf32(acc[mg][mt], af, bf);
            }
    }

    // ---- register softmax (4 lanes sharing r hold one row)
    float mx0 = -INFINITY, mx1 = -INFINITY;
#pragma unroll
    for (int mg = 0; mg < 13; mg++)
#pragma unroll
        for (int mt = 0; mt < 2; mt++)
#pragma unroll
            for (int j = 0; j < 2; j++) {
                bool valid = (mg < 12) || (mt == 0 && (2 * tq + j) < 4);
                if (valid) {
                    mx0 = fmaxf(mx0, acc[mg][mt][j]);
                    mx1 = fmaxf(mx1, acc[mg][mt][2 + j]);
                }
            }
    mx0 = fmaxf(mx0, __shfl_xor_sync(0xffffffffu, mx0, 1));
    mx0 = fmaxf(mx0, __shfl_xor_sync(0xffffffffu, mx0, 2));
    mx1 = fmaxf(mx1, __shfl_xor_sync(0xffffffffu, mx1, 1));
    mx1 = fmaxf(mx1, __shfl_xor_sync(0xffffffffu, mx1, 2));

    float sum0 = 0.f, sum1 = 0.f;
#pragma unroll
    for (int mg = 0; mg < 13; mg++)
#pragma unroll
        for (int mt = 0; mt < 2; mt++)
#pragma unroll
            for (int j = 0; j < 2; j++) {
                bool valid = (mg < 12) || (mt == 0 && (2 * tq + j) < 4);
                float e0 = valid ? __expf(acc[mg][mt][j]     - mx0) : 0.f;
                float e1 = valid ? __expf(acc[mg][mt][2 + j] - mx1) : 0.f;
                acc[mg][mt][j]     = e0;
                acc[mg][mt][2 + j] = e1;
                sum0 += e0;
                sum1 += e1;
            }
    sum0 += __shfl_xor_sync(0xffffffffu, sum0, 1);
    sum0 += __shfl_xor_sync(0xffffffffu, sum0, 2);
    sum1 += __shfl_xor_sync(0xffffffffu, sum1, 1);
    sum1 += __shfl_xor_sync(0xffffffffu, sum1, 2);
    const float inv0 = 1.f / sum0;
    const float inv1 = 1.f / sum1;

    // ---- normalize + static_a bias, in registers (P = softmax + A)
    const int row0 = rb + r, row1 = rb + r + 8;
    const float* ar0 = sa + ((size_t)h * SEQ + q0 + row0) * SEQ;
    const float* ar1 = sa + ((size_t)h * SEQ + q0 + row1) * SEQ;
    const bool rOk0 = row0 < 98, rOk1 = row1 < 98;
#pragma unroll
    for (int mg = 0; mg < 13; mg++)
#pragma unroll
        for (int mt = 0; mt < 2; mt++) {
            int c = mg * 16 + mt * 8 + 2 * tq;
#pragma unroll
            for (int j = 0; j < 2; j++) {
                bool valid = (mg < 12) || (mt == 0 && (2 * tq + j) < 4);
                float a0 = (valid && rOk0) ? ar0[c + j] : 0.f;
                float a1 = (valid && rOk1) ? ar1[c + j] : 0.f;
                acc[mg][mt][j]     = valid ? acc[mg][mt][j]     * inv0 + a0 : 0.f;
                acc[mg][mt][2 + j] = valid ? acc[mg][mt][2 + j] * inv1 + a1 : 0.f;
            }
        }

    // ---- swap K -> V in the shared union buffer
    __syncthreads();   // all warps done reading Ks
    for (int i = tid; i < 208 * 16; i += 224) {
        int row = i >> 4, c4 = (i & 15) * 4;
        float4 v = make_float4(0.f, 0.f, 0.f, 0.f);
        if (row < SEQ) v = *(const float4*)(Vg + (size_t)row * QKV3 + c4);
        uint4 o;
        o.x = f2tf32(v.x); o.y = f2tf32(v.y);
        o.z = f2tf32(v.z); o.w = f2tf32(v.w);
        *(uint4*)&Vs[row * 72 + c4] = o;
    }
    __syncthreads();

    // ---- AV: convert each P block (C-frag) to A-frag via quad shuffles,
    //      mma against V. k-chunk kc = mg*2+mt covers S cols kb..kb+7.
    //      A-frag col tq   lives in lane (lane&~3)|(tq>>1),   elem j=tq&1
    //      A-frag col tq+4 lives in lane (lane&~3)|(tq>>1)+2, elem j=tq&1
    float out[8][4];
#pragma unroll
    for (int nt = 0; nt < 8; nt++)
#pragma unroll
        for (int t = 0; t < 4; t++) out[nt][t] = 0.f;

    const int srcA = (lane & ~3) | (tq >> 1);
    const int srcB = srcA + 2;
    const bool jsel = (tq & 1);

#pragma unroll
    for (int mg = 0; mg < 13; mg++) {
#pragma unroll
        for (int mt = 0; mt < 2; mt++) {
            float p0a = __shfl_sync(0xffffffffu, acc[mg][mt][0], srcA);
            float p1a = __shfl_sync(0xffffffffu, acc[mg][mt][1], srcA);
            float p0b = __shfl_sync(0xffffffffu, acc[mg][mt][0], srcB);
            float p1b = __shfl_sync(0xffffffffu, acc[mg][mt][1], srcB);
            float p2a = __shfl_sync(0xffffffffu, acc[mg][mt][2], srcA);
            float p3a = __shfl_sync(0xffffffffu, acc[mg][mt][3], srcA);
            float p2b = __shfl_sync(0xffffffffu, acc[mg][mt][2], srcB);
            float p3b = __shfl_sync(0xffffffffu, acc[mg][mt][3], srcB);
            unsigned af[4];
            af[0] = f2tf32(jsel ? p1a : p0a);   // row r,   col kb+tq
            af[1] = f2tf32(jsel ? p3a : p2a);   // row r+8, col kb+tq
            af[2] = f2tf32(jsel ? p1b : p0b);   // row r,   col kb+tq+4
            af[3] = f2tf32(jsel ? p3b : p2b);   // row r+8, col kb+tq+4
            const int kb = mg * 16 + mt * 8;
#pragma unroll
            for (int nt = 0; nt < 8; nt++) {
                unsigned bf[2];
                bf[0] = Vs[(kb + tq)     * 72 + nt * 8 + r];
                bf[1] = Vs[(kb + tq + 4) * 72 + nt * 8 + r];
                mma_tf32(out[nt], af, bf);
            }
        }
    }

    // ---- store out strip
    float* og = ao + (size_t)b * SEQ * DIMC + h * HD;
#pragma unroll
    for (int nt = 0; nt < 8; nt++) {
        int c = nt * 8 + 2 * tq;
        if (rOk0)
            *(float2*)(og + (size_t)(q0 + row0) * DIMC + c) =
                make_float2(out[nt][0], out[nt][1]);
        if (rOk1)
            *(float2*)(og + (size_t)(q0 + row1) * DIMC + c) =
                make_float2(out[nt][2], out[nt][3]);
    }
}

// ---------------- launch ----------------------------------------------------
extern "C" void kernel_launch(void* const* d_in, const int* in_sizes, int n_in,
                              void* d_out, int out_size)
{
    const float* x     = (const float*)d_in[0];  // [64,196,768]
    const float* Wqkv  = (const float*)d_in[1];  // [768,2304]
    const float* sa    = (const float*)d_in[2];  // [1,12,196,196]
    const float* Wproj = (const float*)d_in[3];  // [768,768]
    const float* bproj = (const float*)d_in[4];  // [768]
    float* out = (float*)d_out;                  // [64,196,768]

    void *p_qkv, *p_ao;
    cudaGetSymbolAddress(&p_qkv, g_qkv);
    cudaGetSymbolAddress(&p_ao, g_ao);
    float* qkv = (float*)p_qkv;
    float* ao  = (float*)p_ao;

    static int smem_set = 0;
    if (!smem_set) {
        cudaFuncSetAttribute(attn_fused_kernel,
                             cudaFuncAttributeMaxDynamicSharedMemorySize,
                             FA_SMEM_BYTES);
        smem_set = 1;
    }

    // 1) QKV GEMM
    gemm_tf32_kernel<<<dim3(QKV3 / TBN, BN / TBM), 256>>>(x, Wqkv, nullptr, qkv,
                                                          BN, QKV3, DIMC, 0);
    // 2) fused scores + register softmax + bias + AV (no S round-trip)
    attn_fused_kernel<<<NBLK, 224, FA_SMEM_BYTES>>>(qkv, sa, ao);
    // 3) output projection + bias
    gemm_tf32_kernel<<<dim3(DIMC / TBN, BN / TBM), 256>>>(ao, Wproj, bproj, out,
                                                          BN, DIMC, DIMC, 1);
}